// round 13
// baseline (speedup 1.0000x reference)
#include <cuda_runtime.h>
#include <cuda_bf16.h>

#define NN 50000
#define EE 800000
#define MAXPOS 5120

// ---------------- device scratch ----------------
// Cbuf row per text-id (1280 bytes):
//   [0,512)    TLs : 256 bf16  (|av|-scaled)
//   [512,1024) TRs : 256 bf16  (|av|-scaled)
//   [1024,1280) interleaved (yl_d f32, yr_d f32) d=0..31  (TL2/TR2, unscaled)
__device__ __align__(16) unsigned char d_Cbuf[7001 * 1280];
__device__ float d_Bpack[64 * 576];
__device__ float d_pe[128];
__device__ float d_ea[4][128];
__device__ float d_we1[4][256];
__device__ float d_we2[4][32];
__device__ float d_TyL[3][256];
__device__ float d_TyR[3][256];
__device__ float d_TyL2[3][32];
__device__ float d_TyR2[3][32];
__device__ float d_cl[32];
__device__ float d_cr[32];
__device__ __align__(16) float d_avabs[256];   // |att|
__device__ __align__(16) float d_av4s[256];    // 0.4 * sign(att)
__device__ float d_TLav06[7001];               // 0.6 * att . TL[x0]
__device__ float d_Dz06[12];                   // 0.6 * att . cmb[c]
__device__ int   d_cnt[4];
__device__ int   d_px[NN];
__device__ int   d_deg[NN];
__device__ int   d_rowptr[NN + 1];
__device__ int   d_cursor[NN + 1];
__device__ int   d_bsum[64];
__device__ int2  d_csr[EE];            // .x = x0s | x1s<<13 | t<<15 ; .y = s | t<<20
__device__ __nv_bfloat16 d_xl2h[NN * 32];
__device__ float d_xr2f[NN * 32];
__device__ float d_gsum[32];

// ---------------- helpers ----------------
__device__ __forceinline__ float warp_sum(float v) {
#pragma unroll
    for (int o = 16; o > 0; o >>= 1) v += __shfl_xor_sync(0xffffffffu, v, o);
    return v;
}
__device__ __forceinline__ float warp_max(float v) {
#pragma unroll
    for (int o = 16; o > 0; o >>= 1) v = fmaxf(v, __shfl_xor_sync(0xffffffffu, v, o));
    return v;
}

// ---------------- init ----------------
__global__ void k_init(const int* __restrict__ x, int n) {
    int i = blockIdx.x * 256 + threadIdx.x;
    if (i < n) {
        d_deg[i] = 0;
        d_px[i] = x[2 * i] | (x[2 * i + 1] << 13);
    }
    if (i < 4)  d_cnt[i] = 0;
    if (i < 32) d_gsum[i] = 0.f;
}

__global__ void k_count(const int* __restrict__ ei, const int* __restrict__ ea, int E) {
    __shared__ int c[3];
    if (threadIdx.x < 3) c[threadIdx.x] = 0;
    __syncthreads();
    int e = blockIdx.x * 256 + threadIdx.x;
    if (e < E) {
        atomicAdd(&d_deg[ei[E + e]], 1);
        atomicAdd(&c[ea[2 * e]], 1);
    }
    __syncthreads();
    if (threadIdx.x < 3) atomicAdd(&d_cnt[threadIdx.x], c[threadIdx.x]);
}

// ---------------- precompute ----------------
__global__ void k_pre(const float* __restrict__ pos_table, const float* __restrict__ pos_W,
                      const float* __restrict__ pos_b, const float* __restrict__ flow_emb,
                      const float* __restrict__ type_emb,
                      const float* __restrict__ c1_Wl, const float* __restrict__ c1_bl,
                      const float* __restrict__ c1_Wr, const float* __restrict__ c1_br,
                      const float* __restrict__ c1_We, const float* __restrict__ c2_We,
                      const float* __restrict__ c2_Wl, const float* __restrict__ c2_Wr,
                      const float* __restrict__ c1_bias,
                      const float* __restrict__ c2_bl, const float* __restrict__ c2_br,
                      const float* __restrict__ att, int E) {
    int t = threadIdx.x;  // 256 threads
    if (blockIdx.x > 0) {
        const float* W2 = (blockIdx.x == 1) ? c2_Wl : c2_Wr;
        for (int i = t; i < 2048; i += 256) {
            int k = i >> 5, c = i & 31;
            float s = 0.f;
            const float* wrow = c1_Wl + k * 256;
            for (int j = 0; j < 256; j++) s += wrow[j] * W2[j * 32 + c];
            d_Bpack[k * 576 + 512 + (blockIdx.x - 1) * 32 + c] = s;
        }
        return;
    }
    __shared__ float s_tmp[7];
    {
        float a = att[t];
        d_avabs[t] = fabsf(a);
        d_av4s[t] = copysignf(0.4f, a);
    }
    if (t < 128) {
        const float* pr = pos_table + MAXPOS * 128;
        float s = pos_b[t];
        for (int k = 0; k < 128; k++) s += pr[k] * pos_W[k * 128 + t];
        d_pe[t] = s;
    }
    __syncthreads();
    if (t < 128) {
        float pe = d_pe[t];
        float invE = 1.f / (float)E;
        for (int ty = 0; ty < 3; ty++) d_ea[ty][t] = flow_emb[ty * 128 + t] + pe;
        d_ea[3][t] = pe + ((float)d_cnt[0] * flow_emb[t] +
                           (float)d_cnt[1] * flow_emb[128 + t] +
                           (float)d_cnt[2] * flow_emb[256 + t]) * invE;
    }
    {
        for (int ty = 0; ty < 3; ty++) {
            float sl = c1_bl[t], sr = c1_br[t];
            for (int k = 0; k < 64; k++) {
                float te = type_emb[ty * 64 + k];
                sl += te * c1_Wl[(64 + k) * 256 + t];
                sr += te * c1_Wr[(64 + k) * 256 + t];
            }
            d_TyL[ty][t] = sl; d_TyR[ty][t] = sr;
        }
    }
    __syncthreads();
    {
        for (int ty = 0; ty < 4; ty++) {
            float s = 0.f;
            for (int k = 0; k < 128; k++) s += d_ea[ty][k] * c1_We[k * 256 + t];
            d_we1[ty][t] = s;
        }
    }
    if (t < 32) {
        for (int ty = 0; ty < 4; ty++) {
            float s = 0.f;
            for (int k = 0; k < 128; k++) s += d_ea[ty][k] * c2_We[k * 32 + t];
            d_we2[ty][t] = s;
        }
        float sl = c2_bl[t], sr = c2_br[t];
        for (int k = 0; k < 256; k++) {
            float b = c1_bias[k];
            sl += b * c2_Wl[k * 32 + t];
            sr += b * c2_Wr[k * 32 + t];
        }
        d_cl[t] = sl; d_cr[t] = sr;
    }
    __syncthreads();
    if (t < 7) {
        float s = 0.f;
        if (t < 4) { for (int j = 0; j < 256; j++) s += att[j] * d_we1[t][j]; }
        else       { for (int j = 0; j < 256; j++) s += att[j] * d_TyL[t - 4][j]; }
        s_tmp[t] = s;
    }
    if (t >= 32 && t < 128) {
        int tt = t - 32;
        if (tt < 96) {
            int ty = tt >> 5, c = tt & 31;
            float sl = 0.f, sr = 0.f;
            for (int k = 0; k < 256; k++) {
                float x = d_TyL[ty][k];
                sl += x * c2_Wl[k * 32 + c];
                sr += x * c2_Wr[k * 32 + c];
            }
            d_TyL2[ty][c] = sl; d_TyR2[ty][c] = sr;
        }
    }
    __syncthreads();
    if (t < 12) {
        int tt = (t < 9) ? t / 3 : 3;
        int x1 = (t < 9) ? t % 3 : t - 9;
        d_Dz06[t] = 0.6f * (s_tmp[tt] + s_tmp[4 + x1]);
    }
    for (int i = t; i < 64 * 512; i += 256) {
        int k = i >> 9, j = i & 511;
        d_Bpack[k * 576 + j] = (j < 256) ? c1_Wl[k * 256 + j] : c1_Wr[k * 256 + (j - 256)];
    }
}

// Cbuf = text_emb (Mt x 64) @ Bpack (64 x 576); TL/TR columns scaled by |av|
__global__ void __launch_bounds__(256) k_tables(const float* __restrict__ A, int M) {
    __shared__ __align__(16) float As[64][64];
    __shared__ __align__(16) float Bs[64][64];
    int r0 = blockIdx.x * 64, c0 = blockIdx.y * 64;
    int tid = threadIdx.x;
    for (int idx = tid; idx < 4096; idx += 256) {
        int r = idx >> 6, k = idx & 63;
        As[r][k] = (r0 + r < M) ? A[(r0 + r) * 64 + k] : 0.f;
        Bs[r][k] = d_Bpack[r * 576 + c0 + k];
    }
    __syncthreads();
    int tx = tid & 15, ty = tid >> 4;
    float acc[4][4] = {};
#pragma unroll 4
    for (int k = 0; k < 64; k++) {
        float a0 = As[ty * 4 + 0][k], a1 = As[ty * 4 + 1][k];
        float a2 = As[ty * 4 + 2][k], a3 = As[ty * 4 + 3][k];
        float4 b = *(const float4*)&Bs[k][tx * 4];
        acc[0][0] += a0 * b.x; acc[0][1] += a0 * b.y; acc[0][2] += a0 * b.z; acc[0][3] += a0 * b.w;
        acc[1][0] += a1 * b.x; acc[1][1] += a1 * b.y; acc[1][2] += a1 * b.z; acc[1][3] += a1 * b.w;
        acc[2][0] += a2 * b.x; acc[2][1] += a2 * b.y; acc[2][2] += a2 * b.z; acc[2][3] += a2 * b.w;
        acc[3][0] += a3 * b.x; acc[3][1] += a3 * b.y; acc[3][2] += a3 * b.z; acc[3][3] += a3 * b.w;
    }
    float4 sc4 = make_float4(1.f, 1.f, 1.f, 1.f);
    if (c0 < 512) sc4 = *(const float4*)&d_avabs[(c0 + tx * 4) & 255];
#pragma unroll
    for (int i = 0; i < 4; i++) {
        int r = r0 + ty * 4 + i;
        if (r >= M) continue;
        unsigned char* rowp = d_Cbuf + (size_t)r * 1280;
        if (c0 < 512) {
            __nv_bfloat162 p0 = __floats2bfloat162_rn(acc[i][0] * sc4.x, acc[i][1] * sc4.y);
            __nv_bfloat162 p1 = __floats2bfloat162_rn(acc[i][2] * sc4.z, acc[i][3] * sc4.w);
            __nv_bfloat162* dst = (__nv_bfloat162*)(rowp + (c0 + tx * 4) * 2);
            dst[0] = p0; dst[1] = p1;
        } else {
#pragma unroll
            for (int q = 0; q < 4; q++) {
                int jj = c0 + tx * 4 + q - 512;
                int dd = jj & 31, w = jj >> 5;
                *(float*)(rowp + 1024 + dd * 8 + w * 4) = acc[i][q];
            }
        }
    }
}

// TLav06[r] = 0.6 * att . TL[r]  = 1.5 * sum(av4s_d * TLs[r][d])   (warp per row)
__global__ void k_tlav(int M) {
    int w = (blockIdx.x * 256 + threadIdx.x) >> 5;
    int lane = threadIdx.x & 31;
    if (w >= M) return;
    const unsigned char* row = d_Cbuf + (size_t)w * 1280;
    uint4 tl = *(const uint4*)(row + (lane << 4));
    const __nv_bfloat162* h = (const __nv_bfloat162*)&tl;
    const float* a4 = &d_av4s[lane * 8];
    float s = 0.f;
#pragma unroll
    for (int q = 0; q < 4; q++) {
        float2 f = __bfloat1622float2(h[q]);
        s = fmaf(a4[2 * q], f.x, s);
        s = fmaf(a4[2 * q + 1], f.y, s);
    }
    s = warp_sum(s);
    if (lane == 0) d_TLav06[w] = 1.5f * s;
}

// ---------------- scan1 (per-block inclusive) ----------------
__global__ void k_scan1(int n) {
    __shared__ int wsum[32];
    int i = blockIdx.x * 1024 + threadIdx.x;
    int lane = threadIdx.x & 31, wid = threadIdx.x >> 5;
    int x = (i < n) ? d_deg[i] : 0;
#pragma unroll
    for (int o = 1; o < 32; o <<= 1) {
        int y = __shfl_up_sync(0xffffffffu, x, o);
        if (lane >= o) x += y;
    }
    if (lane == 31) wsum[wid] = x;
    __syncthreads();
    if (wid == 0) {
        int s = wsum[lane];
#pragma unroll
        for (int o = 1; o < 32; o <<= 1) {
            int y = __shfl_up_sync(0xffffffffu, s, o);
            if (lane >= o) s += y;
        }
        wsum[lane] = s;
    }
    __syncthreads();
    int incl = x + (wid > 0 ? wsum[wid - 1] : 0);
    if (i < n) d_rowptr[i + 1] = incl;
    if (threadIdx.x == 1023) d_bsum[blockIdx.x] = incl;
}

// ---------------- scan23 ----------------
__global__ void k_scan23(int n) {
    __shared__ int s_prefix;
    int b = blockIdx.x;
    if (threadIdx.x < 32) {
        int lane = threadIdx.x;
        int v0 = (lane < b) ? d_bsum[lane] : 0;
        int v1 = (lane + 32 < b) ? d_bsum[lane + 32] : 0;
        int s = v0 + v1;
#pragma unroll
        for (int o = 16; o > 0; o >>= 1) s += __shfl_xor_sync(0xffffffffu, s, o);
        if (lane == 0) s_prefix = s;
    }
    __syncthreads();
    int i = b * 1024 + threadIdx.x;
    if (i < n) {
        int val = d_rowptr[i + 1] + s_prefix;
        d_rowptr[i + 1] = val;
        d_cursor[i + 1] = val;
    }
    if (i == 0) { d_rowptr[0] = 0; d_cursor[0] = 0; }
}

__global__ void k_fill(const int* __restrict__ ei, const int* __restrict__ ea, int E) {
    int e = blockIdx.x * 256 + threadIdx.x;
    if (e < E) {
        int s = ei[e];
        int d = ei[E + e];
        int t = ea[2 * e];
        int pos = atomicAdd(&d_cursor[d], 1);
        d_csr[pos] = make_int2(d_px[s] | (t << 15), s | (t << 20));
    }
}

// ---------------- layer 1: persistent warps, quarter-warp abs scores + factored linear ----------------
__global__ void __launch_bounds__(256, 4) k_edge1(int n, int nwarps) {
    __shared__ float s_cmb[12][256];   // |av|*(we1[t]+TyL[x1]); c = t*3+x1s (t<3), 9+x1 self
    __shared__ float s_TyRs[3][256];   // |av|*TyR
    __shared__ __align__(8) float2 s_Ty2[3][32];
    __shared__ __align__(16) float s_av4[256];
    __shared__ __align__(16) float s_xr[8][256];   // per-warp scaled xr
    __shared__ float s_Dz[12];
    __shared__ float s_cl[32], s_cr[32];
    int tid = threadIdx.x;
    for (int i = tid; i < 12 * 256; i += 256) {
        int c = i >> 8, j = i & 255;
        int tt = (c < 9) ? (c / 3) : 3;
        int x1 = (c < 9) ? (c % 3) : (c - 9);
        s_cmb[c][j] = d_avabs[j] * (d_we1[tt][j] + d_TyL[x1][j]);
    }
    for (int i = tid; i < 768; i += 256)
        ((float*)s_TyRs)[i] = d_avabs[i & 255] * ((const float*)d_TyR)[i];
    s_av4[tid] = d_av4s[tid];
    if (tid < 96) {
        int ty = tid >> 5, l = tid & 31;
        s_Ty2[ty][l] = make_float2(d_TyL2[ty][l], d_TyR2[ty][l]);
    }
    if (tid < 32) { s_cl[tid] = d_cl[tid]; s_cr[tid] = d_cr[tid]; }
    if (tid < 12) s_Dz[tid] = d_Dz06[tid];
    __syncthreads();

    int lane = tid & 31;
    int wid = tid >> 5;
    int gwarp = blockIdx.x * 8 + wid;
    int j0 = lane * 8;
    int sub = lane >> 3, sl = lane & 7;
    float* xrw = s_xr[wid];

    for (int v = gwarp; v < n; v += nwarps) {
        int pv = d_px[v];
        int x0v = pv & 8191, x1v = pv >> 13;
        const unsigned char* rowv = d_Cbuf + (size_t)x0v * 1280;

        // xrs (scaled) -> regs + per-warp smem
        float xr8[8];
        {
            uint4 raw = *(const uint4*)(rowv + 512 + (lane << 4));
            const __nv_bfloat162* h = (const __nv_bfloat162*)&raw;
#pragma unroll
            for (int q = 0; q < 4; q++) {
                float2 f = __bfloat1622float2(h[q]);
                xr8[2 * q]     = f.x + s_TyRs[x1v][j0 + 2 * q];
                xr8[2 * q + 1] = f.y + s_TyRs[x1v][j0 + 2 * q + 1];
            }
            *(float4*)&xrw[j0]     = make_float4(xr8[0], xr8[1], xr8[2], xr8[3]);
            *(float4*)&xrw[j0 + 4] = make_float4(xr8[4], xr8[5], xr8[6], xr8[7]);
        }
        __syncwarp();

        // Cz06 = 0.6 * att . xr = 1.5 * sum(av4s * xrs)
        float Cz06;
        {
            float czp = 0.f;
#pragma unroll
            for (int j = 0; j < 8; j++) czp = fmaf(s_av4[j0 + j], xr8[j], czp);
            Cz06 = 1.5f * warp_sum(czp);
        }

        float mmax, lsum, accl, accr;
        {
            // self loop (full-warp)
            uint4 raw = *(const uint4*)(rowv + (lane << 4));
            float2 yv = *(const float2*)(rowv + 1024 + (lane << 3));
            const __nv_bfloat162* h = (const __nv_bfloat162*)&raw;
            const float* cmb = &s_cmb[9 + x1v][j0];
            float ppa = 0.f;
#pragma unroll
            for (int q = 0; q < 4; q++) {
                float2 f = __bfloat1622float2(h[q]);
                ppa = fmaf(s_av4[j0 + 2 * q],     fabsf(f.x + xr8[2 * q]     + cmb[2 * q]),     ppa);
                ppa = fmaf(s_av4[j0 + 2 * q + 1], fabsf(f.y + xr8[2 * q + 1] + cmb[2 * q + 1]), ppa);
            }
            mmax = warp_sum(ppa) + d_TLav06[x0v] + Cz06 + s_Dz[9 + x1v];
            lsum = 1.f;
            float2 t2 = s_Ty2[x1v][lane];
            accl = yv.x + t2.x;
            accr = yv.y + t2.y;
        }

        int p0 = d_rowptr[v], p1 = d_rowptr[v + 1];
        for (int base = p0; base < p1; base += 32) {
            int idx = base + lane;
            int pkl = (idx < p1) ? d_csr[idx].x : 0;
            int cnt = min(32, p1 - base);

            // ---- phase A: quarter-warp (8 lanes/edge, 4 edges/iter) ----
            float myscore = -1e30f;
            for (int it = 0; it < cnt; it += 4) {
                int kk = it + sub; if (kk > cnt - 1) kk = cnt - 1;
                int pk = __shfl_sync(0xffffffffu, pkl, kk);
                int x0s = pk & 8191;
                const unsigned char* row = d_Cbuf + (size_t)x0s * 1280;
                float lin = d_TLav06[x0s];
                int c = (pk >> 15) * 3 + ((pk >> 13) & 3);
                const float* cmbp = s_cmb[c];
                float ppa = 0.f;
#pragma unroll
                for (int q = 0; q < 4; q++) {
                    uint4 w4 = *(const uint4*)(row + (q << 7) + (sl << 4));
                    int db = (q << 6) + (sl << 3);
                    float4 xa = *(const float4*)&xrw[db];
                    float4 xb = *(const float4*)&xrw[db + 4];
                    float4 ca = *(const float4*)&cmbp[db];
                    float4 cb = *(const float4*)&cmbp[db + 4];
                    float4 aa = *(const float4*)&s_av4[db];
                    float4 ab = *(const float4*)&s_av4[db + 4];
                    const __nv_bfloat162* h = (const __nv_bfloat162*)&w4;
                    float2 f0 = __bfloat1622float2(h[0]);
                    float2 f1 = __bfloat1622float2(h[1]);
                    float2 f2 = __bfloat1622float2(h[2]);
                    float2 f3 = __bfloat1622float2(h[3]);
                    ppa = fmaf(aa.x, fabsf(f0.x + xa.x + ca.x), ppa);
                    ppa = fmaf(aa.y, fabsf(f0.y + xa.y + ca.y), ppa);
                    ppa = fmaf(aa.z, fabsf(f1.x + xa.z + ca.z), ppa);
                    ppa = fmaf(aa.w, fabsf(f1.y + xa.w + ca.w), ppa);
                    ppa = fmaf(ab.x, fabsf(f2.x + xb.x + cb.x), ppa);
                    ppa = fmaf(ab.y, fabsf(f2.y + xb.y + cb.y), ppa);
                    ppa = fmaf(ab.z, fabsf(f3.x + xb.z + cb.z), ppa);
                    ppa = fmaf(ab.w, fabsf(f3.y + xb.w + cb.w), ppa);
                }
                ppa += __shfl_xor_sync(0xffffffffu, ppa, 4);
                ppa += __shfl_xor_sync(0xffffffffu, ppa, 2);
                ppa += __shfl_xor_sync(0xffffffffu, ppa, 1);
                float e = ppa + lin + Cz06 + s_Dz[c];
                float got = __shfl_sync(0xffffffffu, e, ((lane - it) << 3) & 31);
                if (lane >= it && lane - it < 4 && lane < cnt) myscore = got;
            }

            // ---- chunk-batched softmax update ----
            float cmax = warp_max(myscore);
            float nm = fmaxf(mmax, cmax);
            float sc = __expf(mmax - nm);
            float w  = __expf(myscore - nm);
            float wsum = warp_sum(w);
            lsum = lsum * sc + wsum;
            accl *= sc; accr *= sc;
            mmax = nm;

            // ---- phase B: weighted aggregation, depth-2 pipelined y gathers ----
            int qa = __shfl_sync(0xffffffffu, pkl, 0);
            int qb = __shfl_sync(0xffffffffu, pkl, (cnt > 1) ? 1 : 0);
            float2 ya = *(const float2*)(d_Cbuf + (size_t)(qa & 8191) * 1280 + 1024 + (lane << 3));
            float2 yb = *(const float2*)(d_Cbuf + (size_t)(qb & 8191) * 1280 + 1024 + (lane << 3));
            for (int k = 0; k < cnt; k++) {
                int pk_c = qa; float2 y_c = ya;
                qa = qb; ya = yb;
                if (k + 2 < cnt) {
                    qb = __shfl_sync(0xffffffffu, pkl, k + 2);
                    yb = *(const float2*)(d_Cbuf + (size_t)(qb & 8191) * 1280 + 1024 + (lane << 3));
                }
                float wk = __shfl_sync(0xffffffffu, w, k);
                int x1s = (pk_c >> 13) & 3;
                float2 t2 = s_Ty2[x1s][lane];
                accl = fmaf(wk, y_c.x + t2.x, accl);
                accr = fmaf(wk, y_c.y + t2.y, accr);
            }
        }
        float inv = 1.f / lsum;
        d_xl2h[v * 32 + lane] = __float2bfloat16(accl * inv + s_cl[lane]);
        d_xr2f[v * 32 + lane] = accr * inv + s_cr[lane];
    }
}

// ---------------- layer 2: persistent warps + global mean (R11) ----------------
__global__ void __launch_bounds__(256, 4) k_edge2(const float* __restrict__ att2,
                                                  const float* __restrict__ bias2, int n,
                                                  int nwarps) {
    __shared__ float s_we[4][32];
    __shared__ float s_red[8][32];
    __shared__ float s_stash[8][32][32];
    int tid = threadIdx.x;
    if (tid < 128) ((float*)s_we)[tid] = ((const float*)d_we2)[tid];
    __syncthreads();
    int lane = tid & 31, wid = tid >> 5;
    int gwarp = blockIdx.x * 8 + wid;

    float a = att2[lane];
    float a6 = 0.6f * a, a4 = 0.4f * a;
    float houtsum = 0.f;

    for (int v = gwarp; v < n; v += nwarps) {
        float xrv = d_xr2f[v * 32 + lane];
        float xlv = __bfloat162float(d_xl2h[v * 32 + lane]);
        float z0 = xlv + xrv + s_we[3][lane];
        float mmax = warp_sum(fmaf(a6, z0, a4 * fabsf(z0)));
        float lsum = 1.f, acc = xlv;
        int p0 = d_rowptr[v], p1 = d_rowptr[v + 1];
        for (int base = p0; base < p1; base += 32) {
            int idx = base + lane;
            int pkl = (idx < p1) ? d_csr[idx].y : 0;
            int cnt = min(32, p1 - base);

            float myscore = -1e30f;
            int pk0 = __shfl_sync(0xffffffffu, pkl, 0);
            int pk1 = __shfl_sync(0xffffffffu, pkl, (cnt > 1) ? 1 : 0);
            float x0 = __bfloat162float(d_xl2h[(pk0 & 0xFFFFF) * 32 + lane]);
            float x1 = __bfloat162float(d_xl2h[(pk1 & 0xFFFFF) * 32 + lane]);
            for (int k = 0; k < cnt; k++) {
                int pk_c = pk0; float xls = x0;
                pk0 = pk1; x0 = x1;
                if (k + 2 < cnt) {
                    pk1 = __shfl_sync(0xffffffffu, pkl, k + 2);
                    x1 = __bfloat162float(d_xl2h[(pk1 & 0xFFFFF) * 32 + lane]);
                }
                s_stash[wid][k][lane] = xls;
                float z = xls + xrv + s_we[pk_c >> 20][lane];
                float e = warp_sum(fmaf(a6, z, a4 * fabsf(z)));
                myscore = (lane == k) ? e : myscore;
            }

            float cmax = warp_max(myscore);
            float nm = fmaxf(mmax, cmax);
            float sc = __expf(mmax - nm);
            float w  = __expf(myscore - nm);
            float wsum = warp_sum(w);
            lsum = lsum * sc + wsum;
            acc *= sc;
            mmax = nm;

            for (int k = 0; k < cnt; k++) {
                float wk = __shfl_sync(0xffffffffu, w, k);
                acc = fmaf(wk, s_stash[wid][k][lane], acc);
            }
        }
        houtsum += acc / lsum + bias2[lane];
    }

    s_red[wid][lane] = houtsum;
    __syncthreads();
    if (wid == 0) {
        float s = 0.f;
#pragma unroll
        for (int w = 0; w < 8; w++) s += s_red[w][lane];
        atomicAdd(&d_gsum[lane], s);
    }
}

// ---------------- final: policy head + softmax ----------------
__global__ void k_final(const float* __restrict__ pW, const float* __restrict__ pb,
                        float* __restrict__ out, float invN) {
    __shared__ float g[32];
    __shared__ float red[64];
    int t = threadIdx.x;
    if (t < 32) g[t] = d_gsum[t] * invN;
    __syncthreads();
    float lg = pb[t];
    for (int j = 0; j < 32; j++) lg += g[j] * pW[j * 64 + t];
    red[t] = lg;
    __syncthreads();
    for (int o = 32; o > 0; o >>= 1) {
        if (t < o) red[t] = fmaxf(red[t], red[t + o]);
        __syncthreads();
    }
    float mx = red[0];
    __syncthreads();
    float ex = expf(lg - mx);
    red[t] = ex;
    __syncthreads();
    for (int o = 32; o > 0; o >>= 1) {
        if (t < o) red[t] += red[t + o];
        __syncthreads();
    }
    out[t] = ex / red[0];
}

// ---------------- launch ----------------
extern "C" void kernel_launch(void* const* d_in, const int* in_sizes, int n_in,
                              void* d_out, int out_size) {
    const int*   x         = (const int*)d_in[0];
    const int*   ei        = (const int*)d_in[1];
    const int*   eat       = (const int*)d_in[2];
    const float* text_emb  = (const float*)d_in[3];
    const float* type_emb  = (const float*)d_in[4];
    const float* flow_emb  = (const float*)d_in[5];
    const float* pos_table = (const float*)d_in[6];
    const float* pos_W     = (const float*)d_in[7];
    const float* pos_b     = (const float*)d_in[8];
    const float* c1_Wl  = (const float*)d_in[9];
    const float* c1_bl  = (const float*)d_in[10];
    const float* c1_Wr  = (const float*)d_in[11];
    const float* c1_br  = (const float*)d_in[12];
    const float* c1_We  = (const float*)d_in[13];
    const float* c1_att = (const float*)d_in[14];
    const float* c1_bias= (const float*)d_in[15];
    const float* c2_Wl  = (const float*)d_in[16];
    const float* c2_bl  = (const float*)d_in[17];
    const float* c2_Wr  = (const float*)d_in[18];
    const float* c2_br  = (const float*)d_in[19];
    const float* c2_We  = (const float*)d_in[20];
    const float* c2_att = (const float*)d_in[21];
    const float* c2_bias= (const float*)d_in[22];
    const float* pW     = (const float*)d_in[23];
    const float* pb     = (const float*)d_in[24];
    float* out = (float*)d_out;

    int N = in_sizes[0] / 2; if (N > NN) N = NN;
    int E = in_sizes[1] / 2; if (E > EE) E = EE;
    int Mt = in_sizes[3] / 64;

    int nb = (N + 255) / 256;
    int eb = (E + 255) / 256;
    int sb = (N + 1023) / 1024;
    int tb = (Mt * 32 + 255) / 256;

    int pblocks = 592;
    int nwarps = pblocks * 8;

    k_init<<<nb, 256>>>(x, N);                                            // 0
    k_count<<<eb, 256>>>(ei, eat, E);                                     // 1
    k_pre<<<3, 256>>>(pos_table, pos_W, pos_b, flow_emb, type_emb,        // 2
                      c1_Wl, c1_bl, c1_Wr, c1_br, c1_We, c2_We,
                      c2_Wl, c2_Wr, c1_bias, c2_bl, c2_br, c1_att, E);
    dim3 g((Mt + 63) / 64, 9);
    k_tables<<<g, 256>>>(text_emb, Mt);                                   // 3
    k_tlav<<<tb, 256>>>(Mt);                                              // 4
    k_scan1<<<sb, 1024>>>(N);                                             // 5
    k_scan23<<<sb, 1024>>>(N);                                            // 6
    k_fill<<<eb, 256>>>(ei, eat, E);                                      // 7
    k_edge1<<<pblocks, 256>>>(N, nwarps);                                 // 8
    k_edge2<<<pblocks, 256>>>(c2_att, c2_bias, N, nwarps);                // 9
    k_final<<<1, 64>>>(pW, pb, out, 1.0f / (float)N);                     // 10
}

// round 14
// speedup vs baseline: 1.2934x; 1.2934x over previous
#include <cuda_runtime.h>
#include <cuda_bf16.h>

#define NN 50000
#define EE 800000
#define MAXPOS 5120

// ---------------- device scratch ----------------
__device__ __align__(16) unsigned char d_Cbuf[7001 * 1280];
__device__ float d_Bpack[64 * 576];
__device__ float d_pe[128];
__device__ float d_ea[4][128];
__device__ float d_we1[4][256];
__device__ float d_we2[4][32];
__device__ float d_TyL[3][256];
__device__ float d_TyR[3][256];
__device__ float d_TyL2[3][32];
__device__ float d_TyR2[3][32];
__device__ float d_cl[32];
__device__ float d_cr[32];
__device__ int   d_cnt[4];
__device__ int   d_px[NN];
__device__ int   d_deg[NN];
__device__ int   d_rowptr[NN + 1];
__device__ int   d_cursor[NN + 1];
__device__ int   d_bsum[64];
__device__ int2  d_csr[EE];            // .x = x0s | x1s<<13 | t<<15 ; .y = s | t<<20
__device__ __nv_bfloat16 d_xl2h[NN * 32];
__device__ float d_xr2f[NN * 32];
__device__ float d_gsum[32];

// ---------------- helpers ----------------
__device__ __forceinline__ float warp_sum(float v) {
#pragma unroll
    for (int o = 16; o > 0; o >>= 1) v += __shfl_xor_sync(0xffffffffu, v, o);
    return v;
}
__device__ __forceinline__ float warp_max(float v) {
#pragma unroll
    for (int o = 16; o > 0; o >>= 1) v = fmaxf(v, __shfl_xor_sync(0xffffffffu, v, o));
    return v;
}

// ---------------- init ----------------
__global__ void k_init(const int* __restrict__ x, int n) {
    int i = blockIdx.x * 256 + threadIdx.x;
    if (i < n) {
        d_deg[i] = 0;
        d_px[i] = x[2 * i] | (x[2 * i + 1] << 13);
    }
    if (i < 4)  d_cnt[i] = 0;
    if (i < 32) d_gsum[i] = 0.f;
}

__global__ void k_count(const int* __restrict__ ei, const int* __restrict__ ea, int E) {
    __shared__ int c[3];
    if (threadIdx.x < 3) c[threadIdx.x] = 0;
    __syncthreads();
    int e = blockIdx.x * 256 + threadIdx.x;
    if (e < E) {
        atomicAdd(&d_deg[ei[E + e]], 1);
        atomicAdd(&c[ea[2 * e]], 1);
    }
    __syncthreads();
    if (threadIdx.x < 3) atomicAdd(&d_cnt[threadIdx.x], c[threadIdx.x]);
}

// ---------------- precompute ----------------
__global__ void k_pre(const float* __restrict__ pos_table, const float* __restrict__ pos_W,
                      const float* __restrict__ pos_b, const float* __restrict__ flow_emb,
                      const float* __restrict__ type_emb,
                      const float* __restrict__ c1_Wl, const float* __restrict__ c1_bl,
                      const float* __restrict__ c1_Wr, const float* __restrict__ c1_br,
                      const float* __restrict__ c1_We, const float* __restrict__ c2_We,
                      const float* __restrict__ c2_Wl, const float* __restrict__ c2_Wr,
                      const float* __restrict__ c1_bias,
                      const float* __restrict__ c2_bl, const float* __restrict__ c2_br,
                      int E) {
    int t = threadIdx.x;  // 256 threads
    if (blockIdx.x > 0) {
        const float* W2 = (blockIdx.x == 1) ? c2_Wl : c2_Wr;
        for (int i = t; i < 2048; i += 256) {
            int k = i >> 5, c = i & 31;
            float s = 0.f;
            const float* wrow = c1_Wl + k * 256;
            for (int j = 0; j < 256; j++) s += wrow[j] * W2[j * 32 + c];
            d_Bpack[k * 576 + 512 + (blockIdx.x - 1) * 32 + c] = s;
        }
        return;
    }
    if (t < 128) {
        const float* pr = pos_table + MAXPOS * 128;
        float s = pos_b[t];
        for (int k = 0; k < 128; k++) s += pr[k] * pos_W[k * 128 + t];
        d_pe[t] = s;
    }
    __syncthreads();
    if (t < 128) {
        float pe = d_pe[t];
        float invE = 1.f / (float)E;
        for (int ty = 0; ty < 3; ty++) d_ea[ty][t] = flow_emb[ty * 128 + t] + pe;
        d_ea[3][t] = pe + ((float)d_cnt[0] * flow_emb[t] +
                           (float)d_cnt[1] * flow_emb[128 + t] +
                           (float)d_cnt[2] * flow_emb[256 + t]) * invE;
    }
    {
        for (int ty = 0; ty < 3; ty++) {
            float sl = c1_bl[t], sr = c1_br[t];
            for (int k = 0; k < 64; k++) {
                float te = type_emb[ty * 64 + k];
                sl += te * c1_Wl[(64 + k) * 256 + t];
                sr += te * c1_Wr[(64 + k) * 256 + t];
            }
            d_TyL[ty][t] = sl; d_TyR[ty][t] = sr;
        }
    }
    __syncthreads();
    {
        for (int ty = 0; ty < 4; ty++) {
            float s = 0.f;
            for (int k = 0; k < 128; k++) s += d_ea[ty][k] * c1_We[k * 256 + t];
            d_we1[ty][t] = s;
        }
    }
    if (t < 32) {
        for (int ty = 0; ty < 4; ty++) {
            float s = 0.f;
            for (int k = 0; k < 128; k++) s += d_ea[ty][k] * c2_We[k * 32 + t];
            d_we2[ty][t] = s;
        }
        float sl = c2_bl[t], sr = c2_br[t];
        for (int k = 0; k < 256; k++) {
            float b = c1_bias[k];
            sl += b * c2_Wl[k * 32 + t];
            sr += b * c2_Wr[k * 32 + t];
        }
        d_cl[t] = sl; d_cr[t] = sr;
    }
    __syncthreads();
    if (t < 96) {
        int ty = t >> 5, c = t & 31;
        float sl = 0.f, sr = 0.f;
        for (int k = 0; k < 256; k++) {
            float x = d_TyL[ty][k];
            sl += x * c2_Wl[k * 32 + c];
            sr += x * c2_Wr[k * 32 + c];
        }
        d_TyL2[ty][c] = sl; d_TyR2[ty][c] = sr;
    }
    for (int i = t; i < 64 * 512; i += 256) {
        int k = i >> 9, j = i & 511;
        d_Bpack[k * 576 + j] = (j < 256) ? c1_Wl[k * 256 + j] : c1_Wr[k * 256 + (j - 256)];
    }
}

// Cbuf = text_emb (Mt x 64) @ Bpack (64 x 576)
__global__ void __launch_bounds__(256) k_tables(const float* __restrict__ A, int M) {
    __shared__ __align__(16) float As[64][64];
    __shared__ __align__(16) float Bs[64][64];
    int r0 = blockIdx.x * 64, c0 = blockIdx.y * 64;
    int tid = threadIdx.x;
    for (int idx = tid; idx < 4096; idx += 256) {
        int r = idx >> 6, k = idx & 63;
        As[r][k] = (r0 + r < M) ? A[(r0 + r) * 64 + k] : 0.f;
        Bs[r][k] = d_Bpack[r * 576 + c0 + k];
    }
    __syncthreads();
    int tx = tid & 15, ty = tid >> 4;
    float acc[4][4] = {};
#pragma unroll 4
    for (int k = 0; k < 64; k++) {
        float a0 = As[ty * 4 + 0][k], a1 = As[ty * 4 + 1][k];
        float a2 = As[ty * 4 + 2][k], a3 = As[ty * 4 + 3][k];
        float4 b = *(const float4*)&Bs[k][tx * 4];
        acc[0][0] += a0 * b.x; acc[0][1] += a0 * b.y; acc[0][2] += a0 * b.z; acc[0][3] += a0 * b.w;
        acc[1][0] += a1 * b.x; acc[1][1] += a1 * b.y; acc[1][2] += a1 * b.z; acc[1][3] += a1 * b.w;
        acc[2][0] += a2 * b.x; acc[2][1] += a2 * b.y; acc[2][2] += a2 * b.z; acc[2][3] += a2 * b.w;
        acc[3][0] += a3 * b.x; acc[3][1] += a3 * b.y; acc[3][2] += a3 * b.z; acc[3][3] += a3 * b.w;
    }
#pragma unroll
    for (int i = 0; i < 4; i++) {
        int r = r0 + ty * 4 + i;
        if (r >= M) continue;
        unsigned char* rowp = d_Cbuf + (size_t)r * 1280;
        if (c0 < 512) {
            __nv_bfloat162 p0 = __floats2bfloat162_rn(acc[i][0], acc[i][1]);
            __nv_bfloat162 p1 = __floats2bfloat162_rn(acc[i][2], acc[i][3]);
            __nv_bfloat162* dst = (__nv_bfloat162*)(rowp + (c0 + tx * 4) * 2);
            dst[0] = p0; dst[1] = p1;
        } else {
#pragma unroll
            for (int q = 0; q < 4; q++) {
                int jj = c0 + tx * 4 + q - 512;
                int dd = jj & 31, w = jj >> 5;
                *(float*)(rowp + 1024 + dd * 8 + w * 4) = acc[i][q];
            }
        }
    }
}

// ---------------- scan1 (per-block inclusive) ----------------
__global__ void k_scan1(int n) {
    __shared__ int wsum[32];
    int i = blockIdx.x * 1024 + threadIdx.x;
    int lane = threadIdx.x & 31, wid = threadIdx.x >> 5;
    int x = (i < n) ? d_deg[i] : 0;
#pragma unroll
    for (int o = 1; o < 32; o <<= 1) {
        int y = __shfl_up_sync(0xffffffffu, x, o);
        if (lane >= o) x += y;
    }
    if (lane == 31) wsum[wid] = x;
    __syncthreads();
    if (wid == 0) {
        int s = wsum[lane];
#pragma unroll
        for (int o = 1; o < 32; o <<= 1) {
            int y = __shfl_up_sync(0xffffffffu, s, o);
            if (lane >= o) s += y;
        }
        wsum[lane] = s;
    }
    __syncthreads();
    int incl = x + (wid > 0 ? wsum[wid - 1] : 0);
    if (i < n) d_rowptr[i + 1] = incl;
    if (threadIdx.x == 1023) d_bsum[blockIdx.x] = incl;
}

// ---------------- scan23: per-block prefix from bsum + apply ----------------
__global__ void k_scan23(int n) {
    __shared__ int s_prefix;
    int b = blockIdx.x;
    if (threadIdx.x < 32) {
        int lane = threadIdx.x;
        int v0 = (lane < b) ? d_bsum[lane] : 0;
        int v1 = (lane + 32 < b) ? d_bsum[lane + 32] : 0;
        int s = v0 + v1;
#pragma unroll
        for (int o = 16; o > 0; o >>= 1) s += __shfl_xor_sync(0xffffffffu, s, o);
        if (lane == 0) s_prefix = s;
    }
    __syncthreads();
    int i = b * 1024 + threadIdx.x;
    if (i < n) {
        int val = d_rowptr[i + 1] + s_prefix;
        d_rowptr[i + 1] = val;
        d_cursor[i + 1] = val;
    }
    if (i == 0) { d_rowptr[0] = 0; d_cursor[0] = 0; }
}

__global__ void k_fill(const int* __restrict__ ei, const int* __restrict__ ea, int E) {
    int e = blockIdx.x * 256 + threadIdx.x;
    if (e < E) {
        int s = ei[e];
        int d = ei[E + e];
        int t = ea[2 * e];
        int pos = atomicAdd(&d_cursor[d], 1);
        d_csr[pos] = make_int2(d_px[s] | (t << 15), s | (t << 20));
    }
}

// ---------------- layer 1: PERSISTENT warps (one resident wave), two-phase ----------------
__global__ void __launch_bounds__(256, 4) k_edge1(const float* __restrict__ att, int n,
                                                  int nwarps) {
    __shared__ float s_cmb[12][256];   // t*3+x1s (t<3); 9+x1 self-loop
    __shared__ float s_TyR[3][256];
    __shared__ __align__(8) float2 s_Ty2[3][32];   // (TyL2, TyR2)
    __shared__ float s_cl[32], s_cr[32];
    int tid = threadIdx.x;
    for (int i = tid; i < 12 * 256; i += 256) {
        int c = i >> 8, j = i & 255;
        int tt = (c < 9) ? (c / 3) : 3;
        int x1 = (c < 9) ? (c % 3) : (c - 9);
        s_cmb[c][j] = d_we1[tt][j] + d_TyL[x1][j];
    }
    for (int i = tid; i < 768; i += 256) ((float*)s_TyR)[i] = ((const float*)d_TyR)[i];
    if (tid < 96) {
        int ty = tid >> 5, l = tid & 31;
        s_Ty2[ty][l] = make_float2(d_TyL2[ty][l], d_TyR2[ty][l]);
    }
    if (tid < 32) { s_cl[tid] = d_cl[tid]; s_cr[tid] = d_cr[tid]; }
    __syncthreads();

    int lane = tid & 31;
    int gwarp = blockIdx.x * 8 + (tid >> 5);
    int j0 = lane * 8;

    // loop-invariant attention coefficients
    float av[8];
    {
        float4 a0 = *(const float4*)(att + j0);
        float4 a1 = *(const float4*)(att + j0 + 4);
        av[0] = a0.x; av[1] = a0.y; av[2] = a0.z; av[3] = a0.w;
        av[4] = a1.x; av[5] = a1.y; av[6] = a1.z; av[7] = a1.w;
    }

    for (int v = gwarp; v < n; v += nwarps) {
        int pv = d_px[v];
        int x0v = pv & 8191, x1v = pv >> 13;
        const unsigned char* rowv = d_Cbuf + (size_t)x0v * 1280;

        float xr[8];
        {
            uint4 raw = *(const uint4*)(rowv + 512 + (lane << 4));
            const __nv_bfloat162* h = (const __nv_bfloat162*)&raw;
#pragma unroll
            for (int q = 0; q < 4; q++) {
                float2 f = __bfloat1622float2(h[q]);
                xr[2 * q]     = f.x + s_TyR[x1v][j0 + 2 * q];
                xr[2 * q + 1] = f.y + s_TyR[x1v][j0 + 2 * q + 1];
            }
        }

        float mmax, lsum, accl, accr;
        {
            // self loop
            uint4 raw = *(const uint4*)(rowv + (lane << 4));
            float2 yv = *(const float2*)(rowv + 1024 + (lane << 3));
            const __nv_bfloat162* h = (const __nv_bfloat162*)&raw;
            const float* cmb = &s_cmb[9 + x1v][j0];
            float ppz = 0.f, ppa = 0.f;
#pragma unroll
            for (int q = 0; q < 4; q++) {
                float2 f = __bfloat1622float2(h[q]);
                float zx = f.x + xr[2 * q]     + cmb[2 * q];
                float zy = f.y + xr[2 * q + 1] + cmb[2 * q + 1];
                ppz = fmaf(av[2 * q],     zx, ppz); ppa = fmaf(av[2 * q],     fabsf(zx), ppa);
                ppz = fmaf(av[2 * q + 1], zy, ppz); ppa = fmaf(av[2 * q + 1], fabsf(zy), ppa);
            }
            mmax = warp_sum(fmaf(0.4f, ppa, 0.6f * ppz));
            lsum = 1.f;
            float2 t2 = s_Ty2[x1v][lane];
            accl = yv.x + t2.x;
            accr = yv.y + t2.y;
        }

        int p0 = d_rowptr[v], p1 = d_rowptr[v + 1];
        for (int base = p0; base < p1; base += 32) {
            int idx = base + lane;
            int pkl = (idx < p1) ? d_csr[idx].x : 0;
            int cnt = min(32, p1 - base);

            // ---- phase A: scores, depth-2 pipelined TL gathers ----
            float myscore = -1e30f;
            int pk0 = __shfl_sync(0xffffffffu, pkl, 0);
            int pk1 = __shfl_sync(0xffffffffu, pkl, (cnt > 1) ? 1 : 0);
            uint4 t0 = *(const uint4*)(d_Cbuf + (size_t)(pk0 & 8191) * 1280 + (lane << 4));
            uint4 t1 = *(const uint4*)(d_Cbuf + (size_t)(pk1 & 8191) * 1280 + (lane << 4));
            for (int k = 0; k < cnt; k++) {
                int pk_c = pk0; uint4 tl_c = t0;
                pk0 = pk1; t0 = t1;
                if (k + 2 < cnt) {
                    pk1 = __shfl_sync(0xffffffffu, pkl, k + 2);
                    t1 = *(const uint4*)(d_Cbuf + (size_t)(pk1 & 8191) * 1280 + (lane << 4));
                }
                int x1s = (pk_c >> 13) & 3;
                int t   = pk_c >> 15;
                const float* cmb = &s_cmb[t * 3 + x1s][j0];
                const __nv_bfloat162* h = (const __nv_bfloat162*)&tl_c;
                float ppz = 0.f, ppa = 0.f;
#pragma unroll
                for (int q = 0; q < 4; q++) {
                    float2 f = __bfloat1622float2(h[q]);
                    float zx = f.x + xr[2 * q]     + cmb[2 * q];
                    float zy = f.y + xr[2 * q + 1] + cmb[2 * q + 1];
                    ppz = fmaf(av[2 * q],     zx, ppz); ppa = fmaf(av[2 * q],     fabsf(zx), ppa);
                    ppz = fmaf(av[2 * q + 1], zy, ppz); ppa = fmaf(av[2 * q + 1], fabsf(zy), ppa);
                }
                float e = warp_sum(fmaf(0.4f, ppa, 0.6f * ppz));
                myscore = (lane == k) ? e : myscore;
            }

            // ---- chunk-batched softmax update ----
            float cmax = warp_max(myscore);
            float nm = fmaxf(mmax, cmax);
            float sc = __expf(mmax - nm);
            float w  = __expf(myscore - nm);
            float wsum = warp_sum(w);
            lsum = lsum * sc + wsum;
            accl *= sc; accr *= sc;
            mmax = nm;

            // ---- phase B: weighted aggregation, depth-2 pipelined y gathers ----
            int qa = __shfl_sync(0xffffffffu, pkl, 0);
            int qb = __shfl_sync(0xffffffffu, pkl, (cnt > 1) ? 1 : 0);
            float2 ya = *(const float2*)(d_Cbuf + (size_t)(qa & 8191) * 1280 + 1024 + (lane << 3));
            float2 yb = *(const float2*)(d_Cbuf + (size_t)(qb & 8191) * 1280 + 1024 + (lane << 3));
            for (int k = 0; k < cnt; k++) {
                int pk_c = qa; float2 y_c = ya;
                qa = qb; ya = yb;
                if (k + 2 < cnt) {
                    qb = __shfl_sync(0xffffffffu, pkl, k + 2);
                    yb = *(const float2*)(d_Cbuf + (size_t)(qb & 8191) * 1280 + 1024 + (lane << 3));
                }
                float wk = __shfl_sync(0xffffffffu, w, k);
                int x1s = (pk_c >> 13) & 3;
                float2 t2 = s_Ty2[x1s][lane];
                accl = fmaf(wk, y_c.x + t2.x, accl);
                accr = fmaf(wk, y_c.y + t2.y, accr);
            }
        }
        float inv = 1.f / lsum;
        d_xl2h[v * 32 + lane] = __float2bfloat16(accl * inv + s_cl[lane]);
        d_xr2f[v * 32 + lane] = accr * inv + s_cr[lane];
    }
}

// ---------------- layer 2: PERSISTENT warps + global mean ----------------
__global__ void __launch_bounds__(256, 4) k_edge2(const float* __restrict__ att2,
                                                  const float* __restrict__ bias2, int n,
                                                  int nwarps) {
    __shared__ float s_we[4][32];
    __shared__ float s_red[8][32];
    __shared__ float s_stash[8][32][32];   // [warp][k][lane]
    int tid = threadIdx.x;
    if (tid < 128) ((float*)s_we)[tid] = ((const float*)d_we2)[tid];
    __syncthreads();
    int lane = tid & 31, wid = tid >> 5;
    int gwarp = blockIdx.x * 8 + wid;

    float a = att2[lane];
    float a6 = 0.6f * a, a4 = 0.4f * a;
    float houtsum = 0.f;

    for (int v = gwarp; v < n; v += nwarps) {
        float xrv = d_xr2f[v * 32 + lane];
        float xlv = __bfloat162float(d_xl2h[v * 32 + lane]);
        float z0 = xlv + xrv + s_we[3][lane];
        float mmax = warp_sum(fmaf(a6, z0, a4 * fabsf(z0)));
        float lsum = 1.f, acc = xlv;
        int p0 = d_rowptr[v], p1 = d_rowptr[v + 1];
        for (int base = p0; base < p1; base += 32) {
            int idx = base + lane;
            int pkl = (idx < p1) ? d_csr[idx].y : 0;
            int cnt = min(32, p1 - base);

            // phase A: scores + stash, depth-2 pipelined gathers
            float myscore = -1e30f;
            int pk0 = __shfl_sync(0xffffffffu, pkl, 0);
            int pk1 = __shfl_sync(0xffffffffu, pkl, (cnt > 1) ? 1 : 0);
            float x0 = __bfloat162float(d_xl2h[(pk0 & 0xFFFFF) * 32 + lane]);
            float x1 = __bfloat162float(d_xl2h[(pk1 & 0xFFFFF) * 32 + lane]);
            for (int k = 0; k < cnt; k++) {
                int pk_c = pk0; float xls = x0;
                pk0 = pk1; x0 = x1;
                if (k + 2 < cnt) {
                    pk1 = __shfl_sync(0xffffffffu, pkl, k + 2);
                    x1 = __bfloat162float(d_xl2h[(pk1 & 0xFFFFF) * 32 + lane]);
                }
                s_stash[wid][k][lane] = xls;
                float z = xls + xrv + s_we[pk_c >> 20][lane];
                float e = warp_sum(fmaf(a6, z, a4 * fabsf(z)));
                myscore = (lane == k) ? e : myscore;
            }

            float cmax = warp_max(myscore);
            float nm = fmaxf(mmax, cmax);
            float sc = __expf(mmax - nm);
            float w  = __expf(myscore - nm);
            float wsum = warp_sum(w);
            lsum = lsum * sc + wsum;
            acc *= sc;
            mmax = nm;

            for (int k = 0; k < cnt; k++) {
                float wk = __shfl_sync(0xffffffffu, w, k);
                acc = fmaf(wk, s_stash[wid][k][lane], acc);
            }
        }
        houtsum += acc / lsum + bias2[lane];
    }

    s_red[wid][lane] = houtsum;
    __syncthreads();
    if (wid == 0) {
        float s = 0.f;
#pragma unroll
        for (int w = 0; w < 8; w++) s += s_red[w][lane];
        atomicAdd(&d_gsum[lane], s);
    }
}

// ---------------- final: policy head + softmax ----------------
__global__ void k_final(const float* __restrict__ pW, const float* __restrict__ pb,
                        float* __restrict__ out, float invN) {
    __shared__ float g[32];
    __shared__ float red[64];
    int t = threadIdx.x;  // 64 threads
    if (t < 32) g[t] = d_gsum[t] * invN;
    __syncthreads();
    float lg = pb[t];
    for (int j = 0; j < 32; j++) lg += g[j] * pW[j * 64 + t];
    red[t] = lg;
    __syncthreads();
    for (int o = 32; o > 0; o >>= 1) {
        if (t < o) red[t] = fmaxf(red[t], red[t + o]);
        __syncthreads();
    }
    float mx = red[0];
    __syncthreads();
    float ex = expf(lg - mx);
    red[t] = ex;
    __syncthreads();
    for (int o = 32; o > 0; o >>= 1) {
        if (t < o) red[t] += red[t + o];
        __syncthreads();
    }
    out[t] = ex / red[0];
}

// ---------------- launch (fork/join: k_tables overlaps scan/fill) ----------------
extern "C" void kernel_launch(void* const* d_in, const int* in_sizes, int n_in,
                              void* d_out, int out_size) {
    const int*   x         = (const int*)d_in[0];
    const int*   ei        = (const int*)d_in[1];
    const int*   eat       = (const int*)d_in[2];
    const float* text_emb  = (const float*)d_in[3];
    const float* type_emb  = (const float*)d_in[4];
    const float* flow_emb  = (const float*)d_in[5];
    const float* pos_table = (const float*)d_in[6];
    const float* pos_W     = (const float*)d_in[7];
    const float* pos_b     = (const float*)d_in[8];
    const float* c1_Wl  = (const float*)d_in[9];
    const float* c1_bl  = (const float*)d_in[10];
    const float* c1_Wr  = (const float*)d_in[11];
    const float* c1_br  = (const float*)d_in[12];
    const float* c1_We  = (const float*)d_in[13];
    const float* c1_att = (const float*)d_in[14];
    const float* c1_bias= (const float*)d_in[15];
    const float* c2_Wl  = (const float*)d_in[16];
    const float* c2_bl  = (const float*)d_in[17];
    const float* c2_Wr  = (const float*)d_in[18];
    const float* c2_br  = (const float*)d_in[19];
    const float* c2_We  = (const float*)d_in[20];
    const float* c2_att = (const float*)d_in[21];
    const float* c2_bias= (const float*)d_in[22];
    const float* pW     = (const float*)d_in[23];
    const float* pb     = (const float*)d_in[24];
    float* out = (float*)d_out;

    int N = in_sizes[0] / 2; if (N > NN) N = NN;
    int E = in_sizes[1] / 2; if (E > EE) E = EE;
    int Mt = in_sizes[3] / 64;

    int nb = (N + 255) / 256;
    int eb = (E + 255) / 256;
    int sb = (N + 1023) / 1024;

    int pblocks = 592;
    int nwarps = pblocks * 8;

    // one-time host objects (no device memory)
    static cudaStream_t s2 = nullptr;
    static cudaEvent_t evFork = nullptr, evJoin = nullptr;
    if (s2 == nullptr) {
        cudaStreamCreateWithFlags(&s2, cudaStreamNonBlocking);
        cudaEventCreateWithFlags(&evFork, cudaEventDisableTiming);
        cudaEventCreateWithFlags(&evJoin, cudaEventDisableTiming);
    }

    k_init<<<nb, 256>>>(x, N);
    k_count<<<eb, 256>>>(ei, eat, E);
    k_pre<<<3, 256>>>(pos_table, pos_W, pos_b, flow_emb, type_emb,
                      c1_Wl, c1_bl, c1_Wr, c1_br, c1_We, c2_We,
                      c2_Wl, c2_Wr, c1_bias, c2_bl, c2_br, E);

    // fork: tables on s2, scan/fill on default
    cudaEventRecord(evFork, 0);
    cudaStreamWaitEvent(s2, evFork, 0);
    dim3 g((Mt + 63) / 64, 9);
    k_tables<<<g, 256, 0, s2>>>(text_emb, Mt);
    cudaEventRecord(evJoin, s2);

    k_scan1<<<sb, 1024>>>(N);
    k_scan23<<<sb, 1024>>>(N);
    k_fill<<<eb, 256>>>(ei, eat, E);

    // join
    cudaStreamWaitEvent(0, evJoin, 0);

    k_edge1<<<pblocks, 256>>>(c1_att, N, nwarps);
    k_edge2<<<pblocks, 256>>>(c2_att, c2_bias, N, nwarps);
    k_final<<<1, 64>>>(pW, pb, out, 1.0f / (float)N);
}

// round 15
// speedup vs baseline: 1.3784x; 1.0657x over previous
#include <cuda_runtime.h>
#include <cuda_bf16.h>

#define NN 50000
#define EE 800000
#define MAXPOS 5120

// ---------------- device scratch ----------------
__device__ __align__(16) unsigned char d_Cbuf[7001 * 1280];
__device__ float d_Bpack[64 * 576];
__device__ float d_pe[128];
__device__ float d_ea[4][128];
__device__ float d_we1[4][256];
__device__ float d_we2[4][32];
__device__ float d_TyL[3][256];
__device__ float d_TyR[3][256];
__device__ float d_TyL2[3][32];
__device__ float d_TyR2[3][32];
__device__ float d_cl[32];
__device__ float d_cr[32];
__device__ int   d_cnt[4];
__device__ int   d_px[NN];
__device__ int   d_deg[NN];
__device__ int   d_rowptr[NN + 1];
__device__ int   d_cursor[NN + 1];
__device__ int   d_bsum[64];
__device__ int2  d_csr[EE];            // .x = x0s | x1s<<13 | t<<15 ; .y = s | t<<20
__device__ __nv_bfloat16 d_xl2h[NN * 32];
__device__ float d_xr2f[NN * 32];
__device__ float d_gsum[32];

// ---------------- helpers ----------------
__device__ __forceinline__ float warp_sum(float v) {
#pragma unroll
    for (int o = 16; o > 0; o >>= 1) v += __shfl_xor_sync(0xffffffffu, v, o);
    return v;
}
__device__ __forceinline__ float warp_max(float v) {
#pragma unroll
    for (int o = 16; o > 0; o >>= 1) v = fmaxf(v, __shfl_xor_sync(0xffffffffu, v, o));
    return v;
}

// ---------------- init ----------------
__global__ void k_init(const int* __restrict__ x, int n) {
    int i = blockIdx.x * 256 + threadIdx.x;
    if (i < n) {
        d_deg[i] = 0;
        d_px[i] = x[2 * i] | (x[2 * i + 1] << 13);
    }
    if (i < 4)  d_cnt[i] = 0;
    if (i < 32) d_gsum[i] = 0.f;
}

__global__ void k_count(const int* __restrict__ ei, const int* __restrict__ ea, int E) {
    __shared__ int c[3];
    if (threadIdx.x < 3) c[threadIdx.x] = 0;
    __syncthreads();
    int e = blockIdx.x * 256 + threadIdx.x;
    if (e < E) {
        atomicAdd(&d_deg[ei[E + e]], 1);
        atomicAdd(&c[ea[2 * e]], 1);
    }
    __syncthreads();
    if (threadIdx.x < 3) atomicAdd(&d_cnt[threadIdx.x], c[threadIdx.x]);
}

// ---------------- precompute ----------------
__global__ void k_pre(const float* __restrict__ pos_table, const float* __restrict__ pos_W,
                      const float* __restrict__ pos_b, const float* __restrict__ flow_emb,
                      const float* __restrict__ type_emb,
                      const float* __restrict__ c1_Wl, const float* __restrict__ c1_bl,
                      const float* __restrict__ c1_Wr, const float* __restrict__ c1_br,
                      const float* __restrict__ c1_We, const float* __restrict__ c2_We,
                      const float* __restrict__ c2_Wl, const float* __restrict__ c2_Wr,
                      const float* __restrict__ c1_bias,
                      const float* __restrict__ c2_bl, const float* __restrict__ c2_br,
                      int E) {
    int t = threadIdx.x;  // 256 threads
    if (blockIdx.x > 0) {
        const float* W2 = (blockIdx.x == 1) ? c2_Wl : c2_Wr;
        for (int i = t; i < 2048; i += 256) {
            int k = i >> 5, c = i & 31;
            float s = 0.f;
            const float* wrow = c1_Wl + k * 256;
            for (int j = 0; j < 256; j++) s += wrow[j] * W2[j * 32 + c];
            d_Bpack[k * 576 + 512 + (blockIdx.x - 1) * 32 + c] = s;
        }
        return;
    }
    if (t < 128) {
        const float* pr = pos_table + MAXPOS * 128;
        float s = pos_b[t];
        for (int k = 0; k < 128; k++) s += pr[k] * pos_W[k * 128 + t];
        d_pe[t] = s;
    }
    __syncthreads();
    if (t < 128) {
        float pe = d_pe[t];
        float invE = 1.f / (float)E;
        for (int ty = 0; ty < 3; ty++) d_ea[ty][t] = flow_emb[ty * 128 + t] + pe;
        d_ea[3][t] = pe + ((float)d_cnt[0] * flow_emb[t] +
                           (float)d_cnt[1] * flow_emb[128 + t] +
                           (float)d_cnt[2] * flow_emb[256 + t]) * invE;
    }
    {
        for (int ty = 0; ty < 3; ty++) {
            float sl = c1_bl[t], sr = c1_br[t];
            for (int k = 0; k < 64; k++) {
                float te = type_emb[ty * 64 + k];
                sl += te * c1_Wl[(64 + k) * 256 + t];
                sr += te * c1_Wr[(64 + k) * 256 + t];
            }
            d_TyL[ty][t] = sl; d_TyR[ty][t] = sr;
        }
    }
    __syncthreads();
    {
        for (int ty = 0; ty < 4; ty++) {
            float s = 0.f;
            for (int k = 0; k < 128; k++) s += d_ea[ty][k] * c1_We[k * 256 + t];
            d_we1[ty][t] = s;
        }
    }
    if (t < 32) {
        for (int ty = 0; ty < 4; ty++) {
            float s = 0.f;
            for (int k = 0; k < 128; k++) s += d_ea[ty][k] * c2_We[k * 32 + t];
            d_we2[ty][t] = s;
        }
        float sl = c2_bl[t], sr = c2_br[t];
        for (int k = 0; k < 256; k++) {
            float b = c1_bias[k];
            sl += b * c2_Wl[k * 32 + t];
            sr += b * c2_Wr[k * 32 + t];
        }
        d_cl[t] = sl; d_cr[t] = sr;
    }
    __syncthreads();
    if (t < 96) {
        int ty = t >> 5, c = t & 31;
        float sl = 0.f, sr = 0.f;
        for (int k = 0; k < 256; k++) {
            float x = d_TyL[ty][k];
            sl += x * c2_Wl[k * 32 + c];
            sr += x * c2_Wr[k * 32 + c];
        }
        d_TyL2[ty][c] = sl; d_TyR2[ty][c] = sr;
    }
    for (int i = t; i < 64 * 512; i += 256) {
        int k = i >> 9, j = i & 511;
        d_Bpack[k * 576 + j] = (j < 256) ? c1_Wl[k * 256 + j] : c1_Wr[k * 256 + (j - 256)];
    }
}

// Cbuf = text_emb (Mt x 64) @ Bpack (64 x 576)
__global__ void __launch_bounds__(256) k_tables(const float* __restrict__ A, int M) {
    __shared__ __align__(16) float As[64][64];
    __shared__ __align__(16) float Bs[64][64];
    int r0 = blockIdx.x * 64, c0 = blockIdx.y * 64;
    int tid = threadIdx.x;
    for (int idx = tid; idx < 4096; idx += 256) {
        int r = idx >> 6, k = idx & 63;
        As[r][k] = (r0 + r < M) ? A[(r0 + r) * 64 + k] : 0.f;
        Bs[r][k] = d_Bpack[r * 576 + c0 + k];
    }
    __syncthreads();
    int tx = tid & 15, ty = tid >> 4;
    float acc[4][4] = {};
#pragma unroll 4
    for (int k = 0; k < 64; k++) {
        float a0 = As[ty * 4 + 0][k], a1 = As[ty * 4 + 1][k];
        float a2 = As[ty * 4 + 2][k], a3 = As[ty * 4 + 3][k];
        float4 b = *(const float4*)&Bs[k][tx * 4];
        acc[0][0] += a0 * b.x; acc[0][1] += a0 * b.y; acc[0][2] += a0 * b.z; acc[0][3] += a0 * b.w;
        acc[1][0] += a1 * b.x; acc[1][1] += a1 * b.y; acc[1][2] += a1 * b.z; acc[1][3] += a1 * b.w;
        acc[2][0] += a2 * b.x; acc[2][1] += a2 * b.y; acc[2][2] += a2 * b.z; acc[2][3] += a2 * b.w;
        acc[3][0] += a3 * b.x; acc[3][1] += a3 * b.y; acc[3][2] += a3 * b.z; acc[3][3] += a3 * b.w;
    }
#pragma unroll
    for (int i = 0; i < 4; i++) {
        int r = r0 + ty * 4 + i;
        if (r >= M) continue;
        unsigned char* rowp = d_Cbuf + (size_t)r * 1280;
        if (c0 < 512) {
            __nv_bfloat162 p0 = __floats2bfloat162_rn(acc[i][0], acc[i][1]);
            __nv_bfloat162 p1 = __floats2bfloat162_rn(acc[i][2], acc[i][3]);
            __nv_bfloat162* dst = (__nv_bfloat162*)(rowp + (c0 + tx * 4) * 2);
            dst[0] = p0; dst[1] = p1;
        } else {
#pragma unroll
            for (int q = 0; q < 4; q++) {
                int jj = c0 + tx * 4 + q - 512;
                int dd = jj & 31, w = jj >> 5;
                *(float*)(rowp + 1024 + dd * 8 + w * 4) = acc[i][q];
            }
        }
    }
}

// ---------------- scan1 (per-block inclusive) ----------------
__global__ void k_scan1(int n) {
    __shared__ int wsum[32];
    int i = blockIdx.x * 1024 + threadIdx.x;
    int lane = threadIdx.x & 31, wid = threadIdx.x >> 5;
    int x = (i < n) ? d_deg[i] : 0;
#pragma unroll
    for (int o = 1; o < 32; o <<= 1) {
        int y = __shfl_up_sync(0xffffffffu, x, o);
        if (lane >= o) x += y;
    }
    if (lane == 31) wsum[wid] = x;
    __syncthreads();
    if (wid == 0) {
        int s = wsum[lane];
#pragma unroll
        for (int o = 1; o < 32; o <<= 1) {
            int y = __shfl_up_sync(0xffffffffu, s, o);
            if (lane >= o) s += y;
        }
        wsum[lane] = s;
    }
    __syncthreads();
    int incl = x + (wid > 0 ? wsum[wid - 1] : 0);
    if (i < n) d_rowptr[i + 1] = incl;
    if (threadIdx.x == 1023) d_bsum[blockIdx.x] = incl;
}

// ---------------- scan23 ----------------
__global__ void k_scan23(int n) {
    __shared__ int s_prefix;
    int b = blockIdx.x;
    if (threadIdx.x < 32) {
        int lane = threadIdx.x;
        int v0 = (lane < b) ? d_bsum[lane] : 0;
        int v1 = (lane + 32 < b) ? d_bsum[lane + 32] : 0;
        int s = v0 + v1;
#pragma unroll
        for (int o = 16; o > 0; o >>= 1) s += __shfl_xor_sync(0xffffffffu, s, o);
        if (lane == 0) s_prefix = s;
    }
    __syncthreads();
    int i = b * 1024 + threadIdx.x;
    if (i < n) {
        int val = d_rowptr[i + 1] + s_prefix;
        d_rowptr[i + 1] = val;
        d_cursor[i + 1] = val;
    }
    if (i == 0) { d_rowptr[0] = 0; d_cursor[0] = 0; }
}

__global__ void k_fill(const int* __restrict__ ei, const int* __restrict__ ea, int E) {
    int e = blockIdx.x * 256 + threadIdx.x;
    if (e < E) {
        int s = ei[e];
        int d = ei[E + e];
        int t = ea[2 * e];
        int pos = atomicAdd(&d_cursor[d], 1);
        d_csr[pos] = make_int2(d_px[s] | (t << 15), s | (t << 20));
    }
}

// ---------------- layer 1: persistent warps, PACKED bf16x2 phase A ----------------
__global__ void __launch_bounds__(256, 4) k_edge1(const float* __restrict__ att, int n,
                                                  int nwarps) {
    __shared__ __align__(16) __nv_bfloat162 s_cmbh[12][128];   // bf16x2 cmb
    __shared__ __align__(16) __nv_bfloat162 s_TyRh[3][128];    // bf16x2 TyR
    __shared__ __align__(8) float2 s_Ty2[3][32];               // (TyL2, TyR2)
    __shared__ float s_cl[32], s_cr[32];
    int tid = threadIdx.x;
    for (int i = tid; i < 12 * 128; i += 256) {
        int c = i >> 7, j = i & 127;
        int tt = (c < 9) ? (c / 3) : 3;
        int x1 = (c < 9) ? (c % 3) : (c - 9);
        s_cmbh[c][j] = __floats2bfloat162_rn(d_we1[tt][2 * j]     + d_TyL[x1][2 * j],
                                             d_we1[tt][2 * j + 1] + d_TyL[x1][2 * j + 1]);
    }
    for (int i = tid; i < 3 * 128; i += 256) {
        int ty = i >> 7, j = i & 127;
        s_TyRh[ty][j] = __floats2bfloat162_rn(d_TyR[ty][2 * j], d_TyR[ty][2 * j + 1]);
    }
    if (tid < 96) {
        int ty = tid >> 5, l = tid & 31;
        s_Ty2[ty][l] = make_float2(d_TyL2[ty][l], d_TyR2[ty][l]);
    }
    if (tid < 32) { s_cl[tid] = d_cl[tid]; s_cr[tid] = d_cr[tid]; }
    __syncthreads();

    int lane = tid & 31;
    int gwarp = blockIdx.x * 8 + (tid >> 5);
    int j0 = lane * 8;    // dim base
    int jh = lane * 4;    // bf16x2 base

    // loop-invariant attention coefficients (packed)
    __nv_bfloat162 av2[4];
#pragma unroll
    for (int q = 0; q < 4; q++)
        av2[q] = __floats2bfloat162_rn(att[j0 + 2 * q], att[j0 + 2 * q + 1]);
    const __nv_bfloat162 zero2 = __float2bfloat162_rn(0.f);

    for (int v = gwarp; v < n; v += nwarps) {
        int pv = d_px[v];
        int x0v = pv & 8191, x1v = pv >> 13;
        const unsigned char* rowv = d_Cbuf + (size_t)x0v * 1280;

        // xr2 = TR2 + TyRh   (packed)
        __nv_bfloat162 xr2[4];
        {
            uint4 raw = *(const uint4*)(rowv + 512 + (lane << 4));
            const __nv_bfloat162* h = (const __nv_bfloat162*)&raw;
#pragma unroll
            for (int q = 0; q < 4; q++) xr2[q] = __hadd2(h[q], s_TyRh[x1v][jh + q]);
        }

        float mmax, lsum, accl, accr;
        {
            // self loop (packed)
            uint4 raw = *(const uint4*)(rowv + (lane << 4));
            float2 yv = *(const float2*)(rowv + 1024 + (lane << 3));
            const __nv_bfloat162* h = (const __nv_bfloat162*)&raw;
            uint4 cm4 = *(const uint4*)&s_cmbh[9 + x1v][jh];
            const __nv_bfloat162* cmh = (const __nv_bfloat162*)&cm4;
            __nv_bfloat162 ppz = zero2, ppa = zero2;
#pragma unroll
            for (int q = 0; q < 4; q++) {
                __nv_bfloat162 z = __hadd2(__hadd2(h[q], xr2[q]), cmh[q]);
                ppz = __hfma2(av2[q], z, ppz);
                ppa = __hfma2(av2[q], __habs2(z), ppa);
            }
            float2 pz = __bfloat1622float2(ppz);
            float2 pa = __bfloat1622float2(ppa);
            mmax = warp_sum(fmaf(0.6f, pz.x + pz.y, 0.4f * (pa.x + pa.y)));
            lsum = 1.f;
            float2 t2 = s_Ty2[x1v][lane];
            accl = yv.x + t2.x;
            accr = yv.y + t2.y;
        }

        int p0 = d_rowptr[v], p1 = d_rowptr[v + 1];
        for (int base = p0; base < p1; base += 32) {
            int idx = base + lane;
            int pkl = (idx < p1) ? d_csr[idx].x : 0;
            int cnt = min(32, p1 - base);

            // ---- phase A: packed scores, depth-2 pipelined TL gathers ----
            float myscore = -1e30f;
            int pk0 = __shfl_sync(0xffffffffu, pkl, 0);
            int pk1 = __shfl_sync(0xffffffffu, pkl, (cnt > 1) ? 1 : 0);
            uint4 t0 = *(const uint4*)(d_Cbuf + (size_t)(pk0 & 8191) * 1280 + (lane << 4));
            uint4 t1 = *(const uint4*)(d_Cbuf + (size_t)(pk1 & 8191) * 1280 + (lane << 4));
            for (int k = 0; k < cnt; k++) {
                int pk_c = pk0; uint4 tl_c = t0;
                pk0 = pk1; t0 = t1;
                if (k + 2 < cnt) {
                    pk1 = __shfl_sync(0xffffffffu, pkl, k + 2);
                    t1 = *(const uint4*)(d_Cbuf + (size_t)(pk1 & 8191) * 1280 + (lane << 4));
                }
                int x1s = (pk_c >> 13) & 3;
                int t   = pk_c >> 15;
                uint4 cm4 = *(const uint4*)&s_cmbh[t * 3 + x1s][jh];
                const __nv_bfloat162* cmh = (const __nv_bfloat162*)&cm4;
                const __nv_bfloat162* h = (const __nv_bfloat162*)&tl_c;
                __nv_bfloat162 ppz = zero2, ppa = zero2;
#pragma unroll
                for (int q = 0; q < 4; q++) {
                    __nv_bfloat162 z = __hadd2(__hadd2(h[q], xr2[q]), cmh[q]);
                    ppz = __hfma2(av2[q], z, ppz);
                    ppa = __hfma2(av2[q], __habs2(z), ppa);
                }
                float2 pz = __bfloat1622float2(ppz);
                float2 pa = __bfloat1622float2(ppa);
                float e = warp_sum(fmaf(0.6f, pz.x + pz.y, 0.4f * (pa.x + pa.y)));
                myscore = (lane == k) ? e : myscore;
            }

            // ---- chunk-batched softmax update ----
            float cmax = warp_max(myscore);
            float nm = fmaxf(mmax, cmax);
            float sc = __expf(mmax - nm);
            float w  = __expf(myscore - nm);
            float wsum = warp_sum(w);
            lsum = lsum * sc + wsum;
            accl *= sc; accr *= sc;
            mmax = nm;

            // ---- phase B: weighted aggregation, depth-2 pipelined y gathers ----
            int qa = __shfl_sync(0xffffffffu, pkl, 0);
            int qb = __shfl_sync(0xffffffffu, pkl, (cnt > 1) ? 1 : 0);
            float2 ya = *(const float2*)(d_Cbuf + (size_t)(qa & 8191) * 1280 + 1024 + (lane << 3));
            float2 yb = *(const float2*)(d_Cbuf + (size_t)(qb & 8191) * 1280 + 1024 + (lane << 3));
            for (int k = 0; k < cnt; k++) {
                int pk_c = qa; float2 y_c = ya;
                qa = qb; ya = yb;
                if (k + 2 < cnt) {
                    qb = __shfl_sync(0xffffffffu, pkl, k + 2);
                    yb = *(const float2*)(d_Cbuf + (size_t)(qb & 8191) * 1280 + 1024 + (lane << 3));
                }
                float wk = __shfl_sync(0xffffffffu, w, k);
                int x1s = (pk_c >> 13) & 3;
                float2 t2 = s_Ty2[x1s][lane];
                accl = fmaf(wk, y_c.x + t2.x, accl);
                accr = fmaf(wk, y_c.y + t2.y, accr);
            }
        }
        float inv = 1.f / lsum;
        d_xl2h[v * 32 + lane] = __float2bfloat16(accl * inv + s_cl[lane]);
        d_xr2f[v * 32 + lane] = accr * inv + s_cr[lane];
    }
}

// ---------------- layer 2: persistent warps + global mean ----------------
__global__ void __launch_bounds__(256, 4) k_edge2(const float* __restrict__ att2,
                                                  const float* __restrict__ bias2, int n,
                                                  int nwarps) {
    __shared__ float s_we[4][32];
    __shared__ float s_red[8][32];
    __shared__ float s_stash[8][32][32];   // [warp][k][lane]
    int tid = threadIdx.x;
    if (tid < 128) ((float*)s_we)[tid] = ((const float*)d_we2)[tid];
    __syncthreads();
    int lane = tid & 31, wid = tid >> 5;
    int gwarp = blockIdx.x * 8 + wid;

    float a = att2[lane];
    float a6 = 0.6f * a, a4 = 0.4f * a;
    float houtsum = 0.f;

    for (int v = gwarp; v < n; v += nwarps) {
        float xrv = d_xr2f[v * 32 + lane];
        float xlv = __bfloat162float(d_xl2h[v * 32 + lane]);
        float z0 = xlv + xrv + s_we[3][lane];
        float mmax = warp_sum(fmaf(a6, z0, a4 * fabsf(z0)));
        float lsum = 1.f, acc = xlv;
        int p0 = d_rowptr[v], p1 = d_rowptr[v + 1];
        for (int base = p0; base < p1; base += 32) {
            int idx = base + lane;
            int pkl = (idx < p1) ? d_csr[idx].y : 0;
            int cnt = min(32, p1 - base);

            // phase A: scores + stash, depth-2 pipelined gathers
            float myscore = -1e30f;
            int pk0 = __shfl_sync(0xffffffffu, pkl, 0);
            int pk1 = __shfl_sync(0xffffffffu, pkl, (cnt > 1) ? 1 : 0);
            float x0 = __bfloat162float(d_xl2h[(pk0 & 0xFFFFF) * 32 + lane]);
            float x1 = __bfloat162float(d_xl2h[(pk1 & 0xFFFFF) * 32 + lane]);
            for (int k = 0; k < cnt; k++) {
                int pk_c = pk0; float xls = x0;
                pk0 = pk1; x0 = x1;
                if (k + 2 < cnt) {
                    pk1 = __shfl_sync(0xffffffffu, pkl, k + 2);
                    x1 = __bfloat162float(d_xl2h[(pk1 & 0xFFFFF) * 32 + lane]);
                }
                s_stash[wid][k][lane] = xls;
                float z = xls + xrv + s_we[pk_c >> 20][lane];
                float e = warp_sum(fmaf(a6, z, a4 * fabsf(z)));
                myscore = (lane == k) ? e : myscore;
            }

            float cmax = warp_max(myscore);
            float nm = fmaxf(mmax, cmax);
            float sc = __expf(mmax - nm);
            float w  = __expf(myscore - nm);
            float wsum = warp_sum(w);
            lsum = lsum * sc + wsum;
            acc *= sc;
            mmax = nm;

            for (int k = 0; k < cnt; k++) {
                float wk = __shfl_sync(0xffffffffu, w, k);
                acc = fmaf(wk, s_stash[wid][k][lane], acc);
            }
        }
        houtsum += acc / lsum + bias2[lane];
    }

    s_red[wid][lane] = houtsum;
    __syncthreads();
    if (wid == 0) {
        float s = 0.f;
#pragma unroll
        for (int w = 0; w < 8; w++) s += s_red[w][lane];
        atomicAdd(&d_gsum[lane], s);
    }
}

// ---------------- final: policy head + softmax ----------------
__global__ void k_final(const float* __restrict__ pW, const float* __restrict__ pb,
                        float* __restrict__ out, float invN) {
    __shared__ float g[32];
    __shared__ float red[64];
    int t = threadIdx.x;  // 64 threads
    if (t < 32) g[t] = d_gsum[t] * invN;
    __syncthreads();
    float lg = pb[t];
    for (int j = 0; j < 32; j++) lg += g[j] * pW[j * 64 + t];
    red[t] = lg;
    __syncthreads();
    for (int o = 32; o > 0; o >>= 1) {
        if (t < o) red[t] = fmaxf(red[t], red[t + o]);
        __syncthreads();
    }
    float mx = red[0];
    __syncthreads();
    float ex = expf(lg - mx);
    red[t] = ex;
    __syncthreads();
    for (int o = 32; o > 0; o >>= 1) {
        if (t < o) red[t] += red[t + o];
        __syncthreads();
    }
    out[t] = ex / red[0];
}

// ---------------- launch (fork/join: k_tables overlaps scan/fill) ----------------
extern "C" void kernel_launch(void* const* d_in, const int* in_sizes, int n_in,
                              void* d_out, int out_size) {
    const int*   x         = (const int*)d_in[0];
    const int*   ei        = (const int*)d_in[1];
    const int*   eat       = (const int*)d_in[2];
    const float* text_emb  = (const float*)d_in[3];
    const float* type_emb  = (const float*)d_in[4];
    const float* flow_emb  = (const float*)d_in[5];
    const float* pos_table = (const float*)d_in[6];
    const float* pos_W     = (const float*)d_in[7];
    const float* pos_b     = (const float*)d_in[8];
    const float* c1_Wl  = (const float*)d_in[9];
    const float* c1_bl  = (const float*)d_in[10];
    const float* c1_Wr  = (const float*)d_in[11];
    const float* c1_br  = (const float*)d_in[12];
    const float* c1_We  = (const float*)d_in[13];
    const float* c1_att = (const float*)d_in[14];
    const float* c1_bias= (const float*)d_in[15];
    const float* c2_Wl  = (const float*)d_in[16];
    const float* c2_bl  = (const float*)d_in[17];
    const float* c2_Wr  = (const float*)d_in[18];
    const float* c2_br  = (const float*)d_in[19];
    const float* c2_We  = (const float*)d_in[20];
    const float* c2_att = (const float*)d_in[21];
    const float* c2_bias= (const float*)d_in[22];
    const float* pW     = (const float*)d_in[23];
    const float* pb     = (const float*)d_in[24];
    float* out = (float*)d_out;

    int N = in_sizes[0] / 2; if (N > NN) N = NN;
    int E = in_sizes[1] / 2; if (E > EE) E = EE;
    int Mt = in_sizes[3] / 64;

    int nb = (N + 255) / 256;
    int eb = (E + 255) / 256;
    int sb = (N + 1023) / 1024;

    int pblocks = 592;
    int nwarps = pblocks * 8;

    // one-time host objects (no device memory)
    static cudaStream_t s2 = nullptr;
    static cudaEvent_t evFork = nullptr, evJoin = nullptr;
    if (s2 == nullptr) {
        cudaStreamCreateWithFlags(&s2, cudaStreamNonBlocking);
        cudaEventCreateWithFlags(&evFork, cudaEventDisableTiming);
        cudaEventCreateWithFlags(&evJoin, cudaEventDisableTiming);
    }

    k_init<<<nb, 256>>>(x, N);
    k_count<<<eb, 256>>>(ei, eat, E);
    k_pre<<<3, 256>>>(pos_table, pos_W, pos_b, flow_emb, type_emb,
                      c1_Wl, c1_bl, c1_Wr, c1_br, c1_We, c2_We,
                      c2_Wl, c2_Wr, c1_bias, c2_bl, c2_br, E);

    // fork: tables on s2, scan/fill on default
    cudaEventRecord(evFork, 0);
    cudaStreamWaitEvent(s2, evFork, 0);
    dim3 g((Mt + 63) / 64, 9);
    k_tables<<<g, 256, 0, s2>>>(text_emb, Mt);
    cudaEventRecord(evJoin, s2);

    k_scan1<<<sb, 1024>>>(N);
    k_scan23<<<sb, 1024>>>(N);
    k_fill<<<eb, 256>>>(ei, eat, E);

    // join
    cudaStreamWaitEvent(0, evJoin, 0);

    k_edge1<<<pblocks, 256>>>(c1_att, N, nwarps);
    k_edge2<<<pblocks, 256>>>(c2_att, c2_bias, N, nwarps);
    k_final<<<1, 64>>>(pW, pb, out, 1.0f / (float)N);
}

// round 16
// speedup vs baseline: 1.5720x; 1.1405x over previous
#include <cuda_runtime.h>
#include <cuda_bf16.h>

#define NN 50000
#define EE 800000
#define MAXPOS 5120

// ---------------- device scratch ----------------
__device__ __align__(16) unsigned char d_Cbuf[7001 * 1280];
__device__ float d_Bpack[64 * 576];
__device__ float d_pe[128];
__device__ float d_ea[4][128];
__device__ float d_we1[4][256];
__device__ float d_we2[4][32];
__device__ float d_TyL[3][256];
__device__ float d_TyR[3][256];
__device__ float d_TyL2[3][32];
__device__ float d_TyR2[3][32];
__device__ float d_cl[32];
__device__ float d_cr[32];
__device__ int   d_cnt[4];
__device__ int   d_px[NN];
__device__ int   d_deg[NN];
__device__ int   d_rowptr[NN + 1];
__device__ int   d_cursor[NN + 1];
__device__ int   d_bsum[64];
__device__ int2  d_csr[EE];            // .x = x0s | x1s<<13 | t<<15 ; .y = s | t<<20
__device__ __nv_bfloat16 d_xl2h[NN * 32];
__device__ float d_xr2f[NN * 32];
__device__ float d_xldot[NN];          // att2 . xl2[v]
__device__ float d_gsum[32];

// ---------------- helpers ----------------
__device__ __forceinline__ float warp_sum(float v) {
#pragma unroll
    for (int o = 16; o > 0; o >>= 1) v += __shfl_xor_sync(0xffffffffu, v, o);
    return v;
}
__device__ __forceinline__ float warp_max(float v) {
#pragma unroll
    for (int o = 16; o > 0; o >>= 1) v = fmaxf(v, __shfl_xor_sync(0xffffffffu, v, o));
    return v;
}

// ---------------- init ----------------
__global__ void k_init(const int* __restrict__ x, int n) {
    int i = blockIdx.x * 256 + threadIdx.x;
    if (i < n) {
        d_deg[i] = 0;
        d_px[i] = x[2 * i] | (x[2 * i + 1] << 13);
    }
    if (i < 4)  d_cnt[i] = 0;
    if (i < 32) d_gsum[i] = 0.f;
}

__global__ void k_count(const int* __restrict__ ei, const int* __restrict__ ea, int E) {
    __shared__ int c[3];
    if (threadIdx.x < 3) c[threadIdx.x] = 0;
    __syncthreads();
    int e = blockIdx.x * 256 + threadIdx.x;
    if (e < E) {
        atomicAdd(&d_deg[ei[E + e]], 1);
        atomicAdd(&c[ea[2 * e]], 1);
    }
    __syncthreads();
    if (threadIdx.x < 3) atomicAdd(&d_cnt[threadIdx.x], c[threadIdx.x]);
}

// ---------------- precompute ----------------
__global__ void k_pre(const float* __restrict__ pos_table, const float* __restrict__ pos_W,
                      const float* __restrict__ pos_b, const float* __restrict__ flow_emb,
                      const float* __restrict__ type_emb,
                      const float* __restrict__ c1_Wl, const float* __restrict__ c1_bl,
                      const float* __restrict__ c1_Wr, const float* __restrict__ c1_br,
                      const float* __restrict__ c1_We, const float* __restrict__ c2_We,
                      const float* __restrict__ c2_Wl, const float* __restrict__ c2_Wr,
                      const float* __restrict__ c1_bias,
                      const float* __restrict__ c2_bl, const float* __restrict__ c2_br,
                      int E) {
    int t = threadIdx.x;  // 256 threads
    if (blockIdx.x > 0) {
        const float* W2 = (blockIdx.x == 1) ? c2_Wl : c2_Wr;
        for (int i = t; i < 2048; i += 256) {
            int k = i >> 5, c = i & 31;
            float s = 0.f;
            const float* wrow = c1_Wl + k * 256;
            for (int j = 0; j < 256; j++) s += wrow[j] * W2[j * 32 + c];
            d_Bpack[k * 576 + 512 + (blockIdx.x - 1) * 32 + c] = s;
        }
        return;
    }
    if (t < 128) {
        const float* pr = pos_table + MAXPOS * 128;
        float s = pos_b[t];
        for (int k = 0; k < 128; k++) s += pr[k] * pos_W[k * 128 + t];
        d_pe[t] = s;
    }
    __syncthreads();
    if (t < 128) {
        float pe = d_pe[t];
        float invE = 1.f / (float)E;
        for (int ty = 0; ty < 3; ty++) d_ea[ty][t] = flow_emb[ty * 128 + t] + pe;
        d_ea[3][t] = pe + ((float)d_cnt[0] * flow_emb[t] +
                           (float)d_cnt[1] * flow_emb[128 + t] +
                           (float)d_cnt[2] * flow_emb[256 + t]) * invE;
    }
    {
        for (int ty = 0; ty < 3; ty++) {
            float sl = c1_bl[t], sr = c1_br[t];
            for (int k = 0; k < 64; k++) {
                float te = type_emb[ty * 64 + k];
                sl += te * c1_Wl[(64 + k) * 256 + t];
                sr += te * c1_Wr[(64 + k) * 256 + t];
            }
            d_TyL[ty][t] = sl; d_TyR[ty][t] = sr;
        }
    }
    __syncthreads();
    {
        for (int ty = 0; ty < 4; ty++) {
            float s = 0.f;
            for (int k = 0; k < 128; k++) s += d_ea[ty][k] * c1_We[k * 256 + t];
            d_we1[ty][t] = s;
        }
    }
    if (t < 32) {
        for (int ty = 0; ty < 4; ty++) {
            float s = 0.f;
            for (int k = 0; k < 128; k++) s += d_ea[ty][k] * c2_We[k * 32 + t];
            d_we2[ty][t] = s;
        }
        float sl = c2_bl[t], sr = c2_br[t];
        for (int k = 0; k < 256; k++) {
            float b = c1_bias[k];
            sl += b * c2_Wl[k * 32 + t];
            sr += b * c2_Wr[k * 32 + t];
        }
        d_cl[t] = sl; d_cr[t] = sr;
    }
    __syncthreads();
    if (t < 96) {
        int ty = t >> 5, c = t & 31;
        float sl = 0.f, sr = 0.f;
        for (int k = 0; k < 256; k++) {
            float x = d_TyL[ty][k];
            sl += x * c2_Wl[k * 32 + c];
            sr += x * c2_Wr[k * 32 + c];
        }
        d_TyL2[ty][c] = sl; d_TyR2[ty][c] = sr;
    }
    for (int i = t; i < 64 * 512; i += 256) {
        int k = i >> 9, j = i & 511;
        d_Bpack[k * 576 + j] = (j < 256) ? c1_Wl[k * 256 + j] : c1_Wr[k * 256 + (j - 256)];
    }
}

// Cbuf = text_emb (Mt x 64) @ Bpack (64 x 576)
__global__ void __launch_bounds__(256) k_tables(const float* __restrict__ A, int M) {
    __shared__ __align__(16) float As[64][64];
    __shared__ __align__(16) float Bs[64][64];
    int r0 = blockIdx.x * 64, c0 = blockIdx.y * 64;
    int tid = threadIdx.x;
    for (int idx = tid; idx < 4096; idx += 256) {
        int r = idx >> 6, k = idx & 63;
        As[r][k] = (r0 + r < M) ? A[(r0 + r) * 64 + k] : 0.f;
        Bs[r][k] = d_Bpack[r * 576 + c0 + k];
    }
    __syncthreads();
    int tx = tid & 15, ty = tid >> 4;
    float acc[4][4] = {};
#pragma unroll 4
    for (int k = 0; k < 64; k++) {
        float a0 = As[ty * 4 + 0][k], a1 = As[ty * 4 + 1][k];
        float a2 = As[ty * 4 + 2][k], a3 = As[ty * 4 + 3][k];
        float4 b = *(const float4*)&Bs[k][tx * 4];
        acc[0][0] += a0 * b.x; acc[0][1] += a0 * b.y; acc[0][2] += a0 * b.z; acc[0][3] += a0 * b.w;
        acc[1][0] += a1 * b.x; acc[1][1] += a1 * b.y; acc[1][2] += a1 * b.z; acc[1][3] += a1 * b.w;
        acc[2][0] += a2 * b.x; acc[2][1] += a2 * b.y; acc[2][2] += a2 * b.z; acc[2][3] += a2 * b.w;
        acc[3][0] += a3 * b.x; acc[3][1] += a3 * b.y; acc[3][2] += a3 * b.z; acc[3][3] += a3 * b.w;
    }
#pragma unroll
    for (int i = 0; i < 4; i++) {
        int r = r0 + ty * 4 + i;
        if (r >= M) continue;
        unsigned char* rowp = d_Cbuf + (size_t)r * 1280;
        if (c0 < 512) {
            __nv_bfloat162 p0 = __floats2bfloat162_rn(acc[i][0], acc[i][1]);
            __nv_bfloat162 p1 = __floats2bfloat162_rn(acc[i][2], acc[i][3]);
            __nv_bfloat162* dst = (__nv_bfloat162*)(rowp + (c0 + tx * 4) * 2);
            dst[0] = p0; dst[1] = p1;
        } else {
#pragma unroll
            for (int q = 0; q < 4; q++) {
                int jj = c0 + tx * 4 + q - 512;
                int dd = jj & 31, w = jj >> 5;
                *(float*)(rowp + 1024 + dd * 8 + w * 4) = acc[i][q];
            }
        }
    }
}

// ---------------- scan1 ----------------
__global__ void k_scan1(int n) {
    __shared__ int wsum[32];
    int i = blockIdx.x * 1024 + threadIdx.x;
    int lane = threadIdx.x & 31, wid = threadIdx.x >> 5;
    int x = (i < n) ? d_deg[i] : 0;
#pragma unroll
    for (int o = 1; o < 32; o <<= 1) {
        int y = __shfl_up_sync(0xffffffffu, x, o);
        if (lane >= o) x += y;
    }
    if (lane == 31) wsum[wid] = x;
    __syncthreads();
    if (wid == 0) {
        int s = wsum[lane];
#pragma unroll
        for (int o = 1; o < 32; o <<= 1) {
            int y = __shfl_up_sync(0xffffffffu, s, o);
            if (lane >= o) s += y;
        }
        wsum[lane] = s;
    }
    __syncthreads();
    int incl = x + (wid > 0 ? wsum[wid - 1] : 0);
    if (i < n) d_rowptr[i + 1] = incl;
    if (threadIdx.x == 1023) d_bsum[blockIdx.x] = incl;
}

// ---------------- scan23 ----------------
__global__ void k_scan23(int n) {
    __shared__ int s_prefix;
    int b = blockIdx.x;
    if (threadIdx.x < 32) {
        int lane = threadIdx.x;
        int v0 = (lane < b) ? d_bsum[lane] : 0;
        int v1 = (lane + 32 < b) ? d_bsum[lane + 32] : 0;
        int s = v0 + v1;
#pragma unroll
        for (int o = 16; o > 0; o >>= 1) s += __shfl_xor_sync(0xffffffffu, s, o);
        if (lane == 0) s_prefix = s;
    }
    __syncthreads();
    int i = b * 1024 + threadIdx.x;
    if (i < n) {
        int val = d_rowptr[i + 1] + s_prefix;
        d_rowptr[i + 1] = val;
        d_cursor[i + 1] = val;
    }
    if (i == 0) { d_rowptr[0] = 0; d_cursor[0] = 0; }
}

__global__ void k_fill(const int* __restrict__ ei, const int* __restrict__ ea, int E) {
    int e = blockIdx.x * 256 + threadIdx.x;
    if (e < E) {
        int s = ei[e];
        int d = ei[E + e];
        int t = ea[2 * e];
        int pos = atomicAdd(&d_cursor[d], 1);
        d_csr[pos] = make_int2(d_px[s] | (t << 15), s | (t << 20));
    }
}

// ---------------- layer 1: persistent warps, packed bf16x2 phase A, + xldot ----------------
__global__ void __launch_bounds__(256, 4) k_edge1(const float* __restrict__ att,
                                                  const float* __restrict__ att2, int n,
                                                  int nwarps) {
    __shared__ __align__(16) __nv_bfloat162 s_cmbh[12][128];
    __shared__ __align__(16) __nv_bfloat162 s_TyRh[3][128];
    __shared__ __align__(8) float2 s_Ty2[3][32];
    __shared__ float s_cl[32], s_cr[32];
    int tid = threadIdx.x;
    for (int i = tid; i < 12 * 128; i += 256) {
        int c = i >> 7, j = i & 127;
        int tt = (c < 9) ? (c / 3) : 3;
        int x1 = (c < 9) ? (c % 3) : (c - 9);
        s_cmbh[c][j] = __floats2bfloat162_rn(d_we1[tt][2 * j]     + d_TyL[x1][2 * j],
                                             d_we1[tt][2 * j + 1] + d_TyL[x1][2 * j + 1]);
    }
    for (int i = tid; i < 3 * 128; i += 256) {
        int ty = i >> 7, j = i & 127;
        s_TyRh[ty][j] = __floats2bfloat162_rn(d_TyR[ty][2 * j], d_TyR[ty][2 * j + 1]);
    }
    if (tid < 96) {
        int ty = tid >> 5, l = tid & 31;
        s_Ty2[ty][l] = make_float2(d_TyL2[ty][l], d_TyR2[ty][l]);
    }
    if (tid < 32) { s_cl[tid] = d_cl[tid]; s_cr[tid] = d_cr[tid]; }
    __syncthreads();

    int lane = tid & 31;
    int gwarp = blockIdx.x * 8 + (tid >> 5);
    int j0 = lane * 8;
    int jh = lane * 4;

    __nv_bfloat162 av2[4];
#pragma unroll
    for (int q = 0; q < 4; q++)
        av2[q] = __floats2bfloat162_rn(att[j0 + 2 * q], att[j0 + 2 * q + 1]);
    const __nv_bfloat162 zero2 = __float2bfloat162_rn(0.f);
    float a2v = att2[lane];

    for (int v = gwarp; v < n; v += nwarps) {
        int pv = d_px[v];
        int x0v = pv & 8191, x1v = pv >> 13;
        const unsigned char* rowv = d_Cbuf + (size_t)x0v * 1280;

        __nv_bfloat162 xr2[4];
        {
            uint4 raw = *(const uint4*)(rowv + 512 + (lane << 4));
            const __nv_bfloat162* h = (const __nv_bfloat162*)&raw;
#pragma unroll
            for (int q = 0; q < 4; q++) xr2[q] = __hadd2(h[q], s_TyRh[x1v][jh + q]);
        }

        float mmax, lsum, accl, accr;
        {
            uint4 raw = *(const uint4*)(rowv + (lane << 4));
            float2 yv = *(const float2*)(rowv + 1024 + (lane << 3));
            const __nv_bfloat162* h = (const __nv_bfloat162*)&raw;
            uint4 cm4 = *(const uint4*)&s_cmbh[9 + x1v][jh];
            const __nv_bfloat162* cmh = (const __nv_bfloat162*)&cm4;
            __nv_bfloat162 ppz = zero2, ppa = zero2;
#pragma unroll
            for (int q = 0; q < 4; q++) {
                __nv_bfloat162 z = __hadd2(__hadd2(h[q], xr2[q]), cmh[q]);
                ppz = __hfma2(av2[q], z, ppz);
                ppa = __hfma2(av2[q], __habs2(z), ppa);
            }
            float2 pz = __bfloat1622float2(ppz);
            float2 pa = __bfloat1622float2(ppa);
            mmax = warp_sum(fmaf(0.6f, pz.x + pz.y, 0.4f * (pa.x + pa.y)));
            lsum = 1.f;
            float2 t2 = s_Ty2[x1v][lane];
            accl = yv.x + t2.x;
            accr = yv.y + t2.y;
        }

        int p0 = d_rowptr[v], p1 = d_rowptr[v + 1];
        for (int base = p0; base < p1; base += 32) {
            int idx = base + lane;
            int pkl = (idx < p1) ? d_csr[idx].x : 0;
            int cnt = min(32, p1 - base);

            float myscore = -1e30f;
            int pk0 = __shfl_sync(0xffffffffu, pkl, 0);
            int pk1 = __shfl_sync(0xffffffffu, pkl, (cnt > 1) ? 1 : 0);
            uint4 t0 = *(const uint4*)(d_Cbuf + (size_t)(pk0 & 8191) * 1280 + (lane << 4));
            uint4 t1 = *(const uint4*)(d_Cbuf + (size_t)(pk1 & 8191) * 1280 + (lane << 4));
            for (int k = 0; k < cnt; k++) {
                int pk_c = pk0; uint4 tl_c = t0;
                pk0 = pk1; t0 = t1;
                if (k + 2 < cnt) {
                    pk1 = __shfl_sync(0xffffffffu, pkl, k + 2);
                    t1 = *(const uint4*)(d_Cbuf + (size_t)(pk1 & 8191) * 1280 + (lane << 4));
                }
                int x1s = (pk_c >> 13) & 3;
                int t   = pk_c >> 15;
                uint4 cm4 = *(const uint4*)&s_cmbh[t * 3 + x1s][jh];
                const __nv_bfloat162* cmh = (const __nv_bfloat162*)&cm4;
                const __nv_bfloat162* h = (const __nv_bfloat162*)&tl_c;
                __nv_bfloat162 ppz = zero2, ppa = zero2;
#pragma unroll
                for (int q = 0; q < 4; q++) {
                    __nv_bfloat162 z = __hadd2(__hadd2(h[q], xr2[q]), cmh[q]);
                    ppz = __hfma2(av2[q], z, ppz);
                    ppa = __hfma2(av2[q], __habs2(z), ppa);
                }
                float2 pz = __bfloat1622float2(ppz);
                float2 pa = __bfloat1622float2(ppa);
                float e = warp_sum(fmaf(0.6f, pz.x + pz.y, 0.4f * (pa.x + pa.y)));
                myscore = (lane == k) ? e : myscore;
            }

            float cmax = warp_max(myscore);
            float nm = fmaxf(mmax, cmax);
            float sc = __expf(mmax - nm);
            float w  = __expf(myscore - nm);
            float wsum = warp_sum(w);
            lsum = lsum * sc + wsum;
            accl *= sc; accr *= sc;
            mmax = nm;

            int qa = __shfl_sync(0xffffffffu, pkl, 0);
            int qb = __shfl_sync(0xffffffffu, pkl, (cnt > 1) ? 1 : 0);
            float2 ya = *(const float2*)(d_Cbuf + (size_t)(qa & 8191) * 1280 + 1024 + (lane << 3));
            float2 yb = *(const float2*)(d_Cbuf + (size_t)(qb & 8191) * 1280 + 1024 + (lane << 3));
            for (int k = 0; k < cnt; k++) {
                int pk_c = qa; float2 y_c = ya;
                qa = qb; ya = yb;
                if (k + 2 < cnt) {
                    qb = __shfl_sync(0xffffffffu, pkl, k + 2);
                    yb = *(const float2*)(d_Cbuf + (size_t)(qb & 8191) * 1280 + 1024 + (lane << 3));
                }
                float wk = __shfl_sync(0xffffffffu, w, k);
                int x1s = (pk_c >> 13) & 3;
                float2 t2 = s_Ty2[x1s][lane];
                accl = fmaf(wk, y_c.x + t2.x, accl);
                accr = fmaf(wk, y_c.y + t2.y, accr);
            }
        }
        float inv = 1.f / lsum;
        float xlval = accl * inv + s_cl[lane];
        __nv_bfloat16 hb = __float2bfloat16(xlval);
        d_xl2h[v * 32 + lane] = hb;
        d_xr2f[v * 32 + lane] = accr * inv + s_cr[lane];
        // xldot for layer-2's factored linear score (uses the bf16-rounded value)
        float xd = warp_sum(a2v * __bfloat162float(hb));
        if (lane == 0) d_xldot[v] = xd;
    }
}

// ---------------- layer 2: transposed phase A (1 edge per lane) ----------------
__global__ void __launch_bounds__(256, 4) k_edge2(const float* __restrict__ att2,
                                                  const float* __restrict__ bias2, int n,
                                                  int nwarps) {
    __shared__ float s_we[4][32];
    __shared__ float s_a[32];
    __shared__ float s_a4[32];
    __shared__ float s_wedot[4];
    __shared__ float s_red[8][32];
    __shared__ __align__(16) uint4 s_stash[8][32][5];   // raw bf16 rows (64B) + 16B pad
    __shared__ float s_zb[8][4][32];                    // per-warp zbase
    int tid = threadIdx.x;
    if (tid < 128) ((float*)s_we)[tid] = ((const float*)d_we2)[tid];
    if (tid < 32) { float a = att2[tid]; s_a[tid] = a; s_a4[tid] = 0.4f * a; }
    __syncthreads();
    if (tid < 4) {
        float s = 0.f;
        for (int d = 0; d < 32; d++) s += s_a[d] * s_we[tid][d];
        s_wedot[tid] = s;
    }
    __syncthreads();
    int lane = tid & 31, wid = tid >> 5;
    int gwarp = blockIdx.x * 8 + wid;

    float a = s_a[lane];
    float a6 = 0.6f * a, a4l = 0.4f * a;
    float houtsum = 0.f;

    for (int v = gwarp; v < n; v += nwarps) {
        float xrv = d_xr2f[v * 32 + lane];
        float (*zb)[32] = s_zb[wid];
#pragma unroll
        for (int t = 0; t < 4; t++) zb[t][lane] = xrv + s_we[t][lane];
        __syncwarp();
        float xrdot = warp_sum(a * xrv);
        float xlv = __bfloat162float(d_xl2h[v * 32 + lane]);
        float z0 = xlv + zb[3][lane];
        float mmax = warp_sum(fmaf(a6, z0, a4l * fabsf(z0)));
        float lsum = 1.f, acc = xlv;
        int p0 = d_rowptr[v], p1 = d_rowptr[v + 1];
        for (int base = p0; base < p1; base += 32) {
            int idx = base + lane;
            bool valid = idx < p1;
            int pk = valid ? d_csr[idx].y : 0;
            int cnt = min(32, p1 - base);
            int s = pk & 0xFFFFF, t = pk >> 20;

            // ---- phase A (transposed): this lane scores its own edge ----
            const uint4* xp = (const uint4*)&d_xl2h[s * 32];
            const float* zbp = zb[t];
            uint4* stp = s_stash[wid][lane];
            float ppa = 0.f;
#pragma unroll
            for (int q = 0; q < 4; q++) {
                uint4 w4 = xp[q];
                stp[q] = w4;
                const __nv_bfloat162* h = (const __nv_bfloat162*)&w4;
#pragma unroll
                for (int r = 0; r < 4; r++) {
                    float2 f = __bfloat1622float2(h[r]);
                    int d = q * 8 + r * 2;
                    float za = f.x + zbp[d];
                    float zc = f.y + zbp[d + 1];
                    ppa = fmaf(s_a4[d],     fabsf(za), ppa);
                    ppa = fmaf(s_a4[d + 1], fabsf(zc), ppa);
                }
            }
            float lin = 0.6f * (d_xldot[s] + xrdot + s_wedot[t]);
            float myscore = valid ? (ppa + lin) : -1e30f;

            // ---- chunk-batched softmax update ----
            float cmax = warp_max(myscore);
            float nm = fmaxf(mmax, cmax);
            float sc = __expf(mmax - nm);
            float w  = __expf(myscore - nm);
            float wsum = warp_sum(w);
            lsum = lsum * sc + wsum;
            acc *= sc;
            mmax = nm;
            __syncwarp();

            // ---- phase B: column reads from stash ----
            for (int k = 0; k < cnt; k++) {
                float wk = __shfl_sync(0xffffffffu, w, k);
                const __nv_bfloat16* row = (const __nv_bfloat16*)s_stash[wid][k];
                acc = fmaf(wk, __bfloat162float(row[lane]), acc);
            }
        }
        houtsum += acc / lsum + bias2[lane];
    }

    s_red[wid][lane] = houtsum;
    __syncthreads();
    if (wid == 0) {
        float s = 0.f;
#pragma unroll
        for (int w = 0; w < 8; w++) s += s_red[w][lane];
        atomicAdd(&d_gsum[lane], s);
    }
}

// ---------------- final: policy head + softmax ----------------
__global__ void k_final(const float* __restrict__ pW, const float* __restrict__ pb,
                        float* __restrict__ out, float invN) {
    __shared__ float g[32];
    __shared__ float red[64];
    int t = threadIdx.x;  // 64 threads
    if (t < 32) g[t] = d_gsum[t] * invN;
    __syncthreads();
    float lg = pb[t];
    for (int j = 0; j < 32; j++) lg += g[j] * pW[j * 64 + t];
    red[t] = lg;
    __syncthreads();
    for (int o = 32; o > 0; o >>= 1) {
        if (t < o) red[t] = fmaxf(red[t], red[t + o]);
        __syncthreads();
    }
    float mx = red[0];
    __syncthreads();
    float ex = expf(lg - mx);
    red[t] = ex;
    __syncthreads();
    for (int o = 32; o > 0; o >>= 1) {
        if (t < o) red[t] += red[t + o];
        __syncthreads();
    }
    out[t] = ex / red[0];
}

// ---------------- launch (fork/join: k_tables overlaps scan/fill) ----------------
extern "C" void kernel_launch(void* const* d_in, const int* in_sizes, int n_in,
                              void* d_out, int out_size) {
    const int*   x         = (const int*)d_in[0];
    const int*   ei        = (const int*)d_in[1];
    const int*   eat       = (const int*)d_in[2];
    const float* text_emb  = (const float*)d_in[3];
    const float* type_emb  = (const float*)d_in[4];
    const float* flow_emb  = (const float*)d_in[5];
    const float* pos_table = (const float*)d_in[6];
    const float* pos_W     = (const float*)d_in[7];
    const float* pos_b     = (const float*)d_in[8];
    const float* c1_Wl  = (const float*)d_in[9];
    const float* c1_bl  = (const float*)d_in[10];
    const float* c1_Wr  = (const float*)d_in[11];
    const float* c1_br  = (const float*)d_in[12];
    const float* c1_We  = (const float*)d_in[13];
    const float* c1_att = (const float*)d_in[14];
    const float* c1_bias= (const float*)d_in[15];
    const float* c2_Wl  = (const float*)d_in[16];
    const float* c2_bl  = (const float*)d_in[17];
    const float* c2_Wr  = (const float*)d_in[18];
    const float* c2_br  = (const float*)d_in[19];
    const float* c2_We  = (const float*)d_in[20];
    const float* c2_att = (const float*)d_in[21];
    const float* c2_bias= (const float*)d_in[22];
    const float* pW     = (const float*)d_in[23];
    const float* pb     = (const float*)d_in[24];
    float* out = (float*)d_out;

    int N = in_sizes[0] / 2; if (N > NN) N = NN;
    int E = in_sizes[1] / 2; if (E > EE) E = EE;
    int Mt = in_sizes[3] / 64;

    int nb = (N + 255) / 256;
    int eb = (E + 255) / 256;
    int sb = (N + 1023) / 1024;

    int pblocks = 592;
    int nwarps = pblocks * 8;

    static cudaStream_t s2 = nullptr;
    static cudaEvent_t evFork = nullptr, evJoin = nullptr;
    if (s2 == nullptr) {
        cudaStreamCreateWithFlags(&s2, cudaStreamNonBlocking);
        cudaEventCreateWithFlags(&evFork, cudaEventDisableTiming);
        cudaEventCreateWithFlags(&evJoin, cudaEventDisableTiming);
    }

    k_init<<<nb, 256>>>(x, N);
    k_count<<<eb, 256>>>(ei, eat, E);
    k_pre<<<3, 256>>>(pos_table, pos_W, pos_b, flow_emb, type_emb,
                      c1_Wl, c1_bl, c1_Wr, c1_br, c1_We, c2_We,
                      c2_Wl, c2_Wr, c1_bias, c2_bl, c2_br, E);

    cudaEventRecord(evFork, 0);
    cudaStreamWaitEvent(s2, evFork, 0);
    dim3 g((Mt + 63) / 64, 9);
    k_tables<<<g, 256, 0, s2>>>(text_emb, Mt);
    cudaEventRecord(evJoin, s2);

    k_scan1<<<sb, 1024>>>(N);
    k_scan23<<<sb, 1024>>>(N);
    k_fill<<<eb, 256>>>(ei, eat, E);

    cudaStreamWaitEvent(0, evJoin, 0);

    k_edge1<<<pblocks, 256>>>(c1_att, c2_att, N, nwarps);
    k_edge2<<<pblocks, 256>>>(c2_att, c2_bias, N, nwarps);
    k_final<<<1, 64>>>(pW, pb, out, 1.0f / (float)N);
}

// round 17
// speedup vs baseline: 1.6117x; 1.0253x over previous
#include <cuda_runtime.h>
#include <cuda_bf16.h>

#define NN 50000
#define EE 800000
#define MAXPOS 5120

// ---------------- device scratch ----------------
__device__ __align__(16) unsigned char d_Cbuf[7001 * 1280];
__device__ float d_Bpack[64 * 576];
__device__ float d_pe[128];
__device__ float d_ea[4][128];
__device__ float d_we1[4][256];
__device__ float d_we2[4][32];
__device__ float d_TyL[3][256];
__device__ float d_TyR[3][256];
__device__ float d_TyL2[3][32];
__device__ float d_TyR2[3][32];
__device__ float d_cl[32];
__device__ float d_cr[32];
__device__ int   d_cnt[4];
__device__ int   d_px[NN];
__device__ int   d_deg[NN];
__device__ int   d_rowptr[NN + 1];
__device__ int   d_cursor[NN + 1];
__device__ int   d_bsum[64];
__device__ int2  d_csr[EE];            // .x = x0s | x1s<<13 | t<<15 ; .y = s | t<<20
__device__ __nv_bfloat16 d_xl2h[NN * 32];
__device__ float d_xr2f[NN * 32];
__device__ float d_xldot[NN];          // att2 . xl2[v]
__device__ float d_gsum[32];

// ---------------- helpers ----------------
__device__ __forceinline__ float warp_sum(float v) {
#pragma unroll
    for (int o = 16; o > 0; o >>= 1) v += __shfl_xor_sync(0xffffffffu, v, o);
    return v;
}
__device__ __forceinline__ float warp_max(float v) {
#pragma unroll
    for (int o = 16; o > 0; o >>= 1) v = fmaxf(v, __shfl_xor_sync(0xffffffffu, v, o));
    return v;
}

// ---------------- init ----------------
__global__ void k_init(const int* __restrict__ x, int n) {
    int i = blockIdx.x * 256 + threadIdx.x;
    if (i < n) {
        d_deg[i] = 0;
        d_px[i] = x[2 * i] | (x[2 * i + 1] << 13);
    }
    if (i < 4)  d_cnt[i] = 0;
    if (i < 32) d_gsum[i] = 0.f;
}

__global__ void k_count(const int* __restrict__ ei, const int* __restrict__ ea, int E) {
    __shared__ int c[3];
    if (threadIdx.x < 3) c[threadIdx.x] = 0;
    __syncthreads();
    int e = blockIdx.x * 256 + threadIdx.x;
    if (e < E) {
        atomicAdd(&d_deg[ei[E + e]], 1);
        atomicAdd(&c[ea[2 * e]], 1);
    }
    __syncthreads();
    if (threadIdx.x < 3) atomicAdd(&d_cnt[threadIdx.x], c[threadIdx.x]);
}

// ---------------- precompute ----------------
__global__ void k_pre(const float* __restrict__ pos_table, const float* __restrict__ pos_W,
                      const float* __restrict__ pos_b, const float* __restrict__ flow_emb,
                      const float* __restrict__ type_emb,
                      const float* __restrict__ c1_Wl, const float* __restrict__ c1_bl,
                      const float* __restrict__ c1_Wr, const float* __restrict__ c1_br,
                      const float* __restrict__ c1_We, const float* __restrict__ c2_We,
                      const float* __restrict__ c2_Wl, const float* __restrict__ c2_Wr,
                      const float* __restrict__ c1_bias,
                      const float* __restrict__ c2_bl, const float* __restrict__ c2_br,
                      int E) {
    int t = threadIdx.x;  // 256 threads
    if (blockIdx.x > 0) {
        const float* W2 = (blockIdx.x == 1) ? c2_Wl : c2_Wr;
        for (int i = t; i < 2048; i += 256) {
            int k = i >> 5, c = i & 31;
            float s = 0.f;
            const float* wrow = c1_Wl + k * 256;
            for (int j = 0; j < 256; j++) s += wrow[j] * W2[j * 32 + c];
            d_Bpack[k * 576 + 512 + (blockIdx.x - 1) * 32 + c] = s;
        }
        return;
    }
    if (t < 128) {
        const float* pr = pos_table + MAXPOS * 128;
        float s = pos_b[t];
        for (int k = 0; k < 128; k++) s += pr[k] * pos_W[k * 128 + t];
        d_pe[t] = s;
    }
    __syncthreads();
    if (t < 128) {
        float pe = d_pe[t];
        float invE = 1.f / (float)E;
        for (int ty = 0; ty < 3; ty++) d_ea[ty][t] = flow_emb[ty * 128 + t] + pe;
        d_ea[3][t] = pe + ((float)d_cnt[0] * flow_emb[t] +
                           (float)d_cnt[1] * flow_emb[128 + t] +
                           (float)d_cnt[2] * flow_emb[256 + t]) * invE;
    }
    {
        for (int ty = 0; ty < 3; ty++) {
            float sl = c1_bl[t], sr = c1_br[t];
            for (int k = 0; k < 64; k++) {
                float te = type_emb[ty * 64 + k];
                sl += te * c1_Wl[(64 + k) * 256 + t];
                sr += te * c1_Wr[(64 + k) * 256 + t];
            }
            d_TyL[ty][t] = sl; d_TyR[ty][t] = sr;
        }
    }
    __syncthreads();
    {
        for (int ty = 0; ty < 4; ty++) {
            float s = 0.f;
            for (int k = 0; k < 128; k++) s += d_ea[ty][k] * c1_We[k * 256 + t];
            d_we1[ty][t] = s;
        }
    }
    if (t < 32) {
        for (int ty = 0; ty < 4; ty++) {
            float s = 0.f;
            for (int k = 0; k < 128; k++) s += d_ea[ty][k] * c2_We[k * 32 + t];
            d_we2[ty][t] = s;
        }
        float sl = c2_bl[t], sr = c2_br[t];
        for (int k = 0; k < 256; k++) {
            float b = c1_bias[k];
            sl += b * c2_Wl[k * 32 + t];
            sr += b * c2_Wr[k * 32 + t];
        }
        d_cl[t] = sl; d_cr[t] = sr;
    }
    __syncthreads();
    if (t < 96) {
        int ty = t >> 5, c = t & 31;
        float sl = 0.f, sr = 0.f;
        for (int k = 0; k < 256; k++) {
            float x = d_TyL[ty][k];
            sl += x * c2_Wl[k * 32 + c];
            sr += x * c2_Wr[k * 32 + c];
        }
        d_TyL2[ty][c] = sl; d_TyR2[ty][c] = sr;
    }
    for (int i = t; i < 64 * 512; i += 256) {
        int k = i >> 9, j = i & 511;
        d_Bpack[k * 576 + j] = (j < 256) ? c1_Wl[k * 256 + j] : c1_Wr[k * 256 + (j - 256)];
    }
}

// Cbuf = text_emb (Mt x 64) @ Bpack (64 x 576)
__global__ void __launch_bounds__(256) k_tables(const float* __restrict__ A, int M) {
    __shared__ __align__(16) float As[64][64];
    __shared__ __align__(16) float Bs[64][64];
    int r0 = blockIdx.x * 64, c0 = blockIdx.y * 64;
    int tid = threadIdx.x;
    for (int idx = tid; idx < 4096; idx += 256) {
        int r = idx >> 6, k = idx & 63;
        As[r][k] = (r0 + r < M) ? A[(r0 + r) * 64 + k] : 0.f;
        Bs[r][k] = d_Bpack[r * 576 + c0 + k];
    }
    __syncthreads();
    int tx = tid & 15, ty = tid >> 4;
    float acc[4][4] = {};
#pragma unroll 4
    for (int k = 0; k < 64; k++) {
        float a0 = As[ty * 4 + 0][k], a1 = As[ty * 4 + 1][k];
        float a2 = As[ty * 4 + 2][k], a3 = As[ty * 4 + 3][k];
        float4 b = *(const float4*)&Bs[k][tx * 4];
        acc[0][0] += a0 * b.x; acc[0][1] += a0 * b.y; acc[0][2] += a0 * b.z; acc[0][3] += a0 * b.w;
        acc[1][0] += a1 * b.x; acc[1][1] += a1 * b.y; acc[1][2] += a1 * b.z; acc[1][3] += a1 * b.w;
        acc[2][0] += a2 * b.x; acc[2][1] += a2 * b.y; acc[2][2] += a2 * b.z; acc[2][3] += a2 * b.w;
        acc[3][0] += a3 * b.x; acc[3][1] += a3 * b.y; acc[3][2] += a3 * b.z; acc[3][3] += a3 * b.w;
    }
#pragma unroll
    for (int i = 0; i < 4; i++) {
        int r = r0 + ty * 4 + i;
        if (r >= M) continue;
        unsigned char* rowp = d_Cbuf + (size_t)r * 1280;
        if (c0 < 512) {
            __nv_bfloat162 p0 = __floats2bfloat162_rn(acc[i][0], acc[i][1]);
            __nv_bfloat162 p1 = __floats2bfloat162_rn(acc[i][2], acc[i][3]);
            __nv_bfloat162* dst = (__nv_bfloat162*)(rowp + (c0 + tx * 4) * 2);
            dst[0] = p0; dst[1] = p1;
        } else {
#pragma unroll
            for (int q = 0; q < 4; q++) {
                int jj = c0 + tx * 4 + q - 512;
                int dd = jj & 31, w = jj >> 5;
                *(float*)(rowp + 1024 + dd * 8 + w * 4) = acc[i][q];
            }
        }
    }
}

// ---------------- scan1 ----------------
__global__ void k_scan1(int n) {
    __shared__ int wsum[32];
    int i = blockIdx.x * 1024 + threadIdx.x;
    int lane = threadIdx.x & 31, wid = threadIdx.x >> 5;
    int x = (i < n) ? d_deg[i] : 0;
#pragma unroll
    for (int o = 1; o < 32; o <<= 1) {
        int y = __shfl_up_sync(0xffffffffu, x, o);
        if (lane >= o) x += y;
    }
    if (lane == 31) wsum[wid] = x;
    __syncthreads();
    if (wid == 0) {
        int s = wsum[lane];
#pragma unroll
        for (int o = 1; o < 32; o <<= 1) {
            int y = __shfl_up_sync(0xffffffffu, s, o);
            if (lane >= o) s += y;
        }
        wsum[lane] = s;
    }
    __syncthreads();
    int incl = x + (wid > 0 ? wsum[wid - 1] : 0);
    if (i < n) d_rowptr[i + 1] = incl;
    if (threadIdx.x == 1023) d_bsum[blockIdx.x] = incl;
}

// ---------------- scan23 ----------------
__global__ void k_scan23(int n) {
    __shared__ int s_prefix;
    int b = blockIdx.x;
    if (threadIdx.x < 32) {
        int lane = threadIdx.x;
        int v0 = (lane < b) ? d_bsum[lane] : 0;
        int v1 = (lane + 32 < b) ? d_bsum[lane + 32] : 0;
        int s = v0 + v1;
#pragma unroll
        for (int o = 16; o > 0; o >>= 1) s += __shfl_xor_sync(0xffffffffu, s, o);
        if (lane == 0) s_prefix = s;
    }
    __syncthreads();
    int i = b * 1024 + threadIdx.x;
    if (i < n) {
        int val = d_rowptr[i + 1] + s_prefix;
        d_rowptr[i + 1] = val;
        d_cursor[i + 1] = val;
    }
    if (i == 0) { d_rowptr[0] = 0; d_cursor[0] = 0; }
}

__global__ void k_fill(const int* __restrict__ ei, const int* __restrict__ ea, int E) {
    int e = blockIdx.x * 256 + threadIdx.x;
    if (e < E) {
        int s = ei[e];
        int d = ei[E + e];
        int t = ea[2 * e];
        int pos = atomicAdd(&d_cursor[d], 1);
        d_csr[pos] = make_int2(d_px[s] | (t << 15), s | (t << 20));
    }
}

// ---------------- layer 1: persistent warps, packed phase A + transpose reduction ----------------
__global__ void __launch_bounds__(256, 4) k_edge1(const float* __restrict__ att,
                                                  const float* __restrict__ att2, int n,
                                                  int nwarps) {
    __shared__ __align__(16) __nv_bfloat162 s_cmbh[12][128];
    __shared__ __align__(16) __nv_bfloat162 s_TyRh[3][128];
    __shared__ __align__(8) float2 s_Ty2[3][32];
    __shared__ float s_cl[32], s_cr[32];
    __shared__ __align__(16) float s_sc[8][32][32];   // [warp][edge][lane] partials
    int tid = threadIdx.x;
    for (int i = tid; i < 12 * 128; i += 256) {
        int c = i >> 7, j = i & 127;
        int tt = (c < 9) ? (c / 3) : 3;
        int x1 = (c < 9) ? (c % 3) : (c - 9);
        s_cmbh[c][j] = __floats2bfloat162_rn(d_we1[tt][2 * j]     + d_TyL[x1][2 * j],
                                             d_we1[tt][2 * j + 1] + d_TyL[x1][2 * j + 1]);
    }
    for (int i = tid; i < 3 * 128; i += 256) {
        int ty = i >> 7, j = i & 127;
        s_TyRh[ty][j] = __floats2bfloat162_rn(d_TyR[ty][2 * j], d_TyR[ty][2 * j + 1]);
    }
    if (tid < 96) {
        int ty = tid >> 5, l = tid & 31;
        s_Ty2[ty][l] = make_float2(d_TyL2[ty][l], d_TyR2[ty][l]);
    }
    if (tid < 32) { s_cl[tid] = d_cl[tid]; s_cr[tid] = d_cr[tid]; }
    __syncthreads();

    int lane = tid & 31;
    int wid = tid >> 5;
    int gwarp = blockIdx.x * 8 + wid;
    int j0 = lane * 8;
    int jh = lane * 4;
    float (*scw)[32] = s_sc[wid];

    __nv_bfloat162 av2[4];
#pragma unroll
    for (int q = 0; q < 4; q++)
        av2[q] = __floats2bfloat162_rn(att[j0 + 2 * q], att[j0 + 2 * q + 1]);
    const __nv_bfloat162 zero2 = __float2bfloat162_rn(0.f);
    float a2v = att2[lane];

    for (int v = gwarp; v < n; v += nwarps) {
        int pv = d_px[v];
        int x0v = pv & 8191, x1v = pv >> 13;
        const unsigned char* rowv = d_Cbuf + (size_t)x0v * 1280;

        __nv_bfloat162 xr2[4];
        {
            uint4 raw = *(const uint4*)(rowv + 512 + (lane << 4));
            const __nv_bfloat162* h = (const __nv_bfloat162*)&raw;
#pragma unroll
            for (int q = 0; q < 4; q++) xr2[q] = __hadd2(h[q], s_TyRh[x1v][jh + q]);
        }

        float mmax, lsum, accl, accr;
        {
            uint4 raw = *(const uint4*)(rowv + (lane << 4));
            float2 yv = *(const float2*)(rowv + 1024 + (lane << 3));
            const __nv_bfloat162* h = (const __nv_bfloat162*)&raw;
            uint4 cm4 = *(const uint4*)&s_cmbh[9 + x1v][jh];
            const __nv_bfloat162* cmh = (const __nv_bfloat162*)&cm4;
            __nv_bfloat162 ppz = zero2, ppa = zero2;
#pragma unroll
            for (int q = 0; q < 4; q++) {
                __nv_bfloat162 z = __hadd2(__hadd2(h[q], xr2[q]), cmh[q]);
                ppz = __hfma2(av2[q], z, ppz);
                ppa = __hfma2(av2[q], __habs2(z), ppa);
            }
            float2 pz = __bfloat1622float2(ppz);
            float2 pa = __bfloat1622float2(ppa);
            mmax = warp_sum(fmaf(0.6f, pz.x + pz.y, 0.4f * (pa.x + pa.y)));
            lsum = 1.f;
            float2 t2 = s_Ty2[x1v][lane];
            accl = yv.x + t2.x;
            accr = yv.y + t2.y;
        }

        int p0 = d_rowptr[v], p1 = d_rowptr[v + 1];
        for (int base = p0; base < p1; base += 32) {
            int idx = base + lane;
            int pkl = (idx < p1) ? d_csr[idx].x : 0;
            int cnt = min(32, p1 - base);

            // ---- phase A: packed partials -> smem stash (no per-edge reduction) ----
            int pk0 = __shfl_sync(0xffffffffu, pkl, 0);
            int pk1 = __shfl_sync(0xffffffffu, pkl, (cnt > 1) ? 1 : 0);
            uint4 t0 = *(const uint4*)(d_Cbuf + (size_t)(pk0 & 8191) * 1280 + (lane << 4));
            uint4 t1 = *(const uint4*)(d_Cbuf + (size_t)(pk1 & 8191) * 1280 + (lane << 4));
            for (int k = 0; k < cnt; k++) {
                int pk_c = pk0; uint4 tl_c = t0;
                pk0 = pk1; t0 = t1;
                if (k + 2 < cnt) {
                    pk1 = __shfl_sync(0xffffffffu, pkl, k + 2);
                    t1 = *(const uint4*)(d_Cbuf + (size_t)(pk1 & 8191) * 1280 + (lane << 4));
                }
                int x1s = (pk_c >> 13) & 3;
                int t   = pk_c >> 15;
                uint4 cm4 = *(const uint4*)&s_cmbh[t * 3 + x1s][jh];
                const __nv_bfloat162* cmh = (const __nv_bfloat162*)&cm4;
                const __nv_bfloat162* h = (const __nv_bfloat162*)&tl_c;
                __nv_bfloat162 ppz = zero2, ppa = zero2;
#pragma unroll
                for (int q = 0; q < 4; q++) {
                    __nv_bfloat162 z = __hadd2(__hadd2(h[q], xr2[q]), cmh[q]);
                    ppz = __hfma2(av2[q], z, ppz);
                    ppa = __hfma2(av2[q], __habs2(z), ppa);
                }
                float2 pz = __bfloat1622float2(ppz);
                float2 pa = __bfloat1622float2(ppa);
                scw[k][lane] = fmaf(0.6f, pz.x + pz.y, 0.4f * (pa.x + pa.y));
            }
            __syncwarp();

            // ---- transpose reduction: lane k sums edge k's partials (rotated, conflict-free) ----
            float myscore = -1e30f;
            if (lane < cnt) {
                const float* rowp = scw[lane];
                float s = 0.f;
#pragma unroll
                for (int j = 0; j < 32; j++) s += rowp[(lane + j) & 31];
                myscore = s;
            }

            // ---- chunk-batched softmax update ----
            float cmax = warp_max(myscore);
            float nm = fmaxf(mmax, cmax);
            float sc = __expf(mmax - nm);
            float w  = __expf(myscore - nm);
            float wsum = warp_sum(w);
            lsum = lsum * sc + wsum;
            accl *= sc; accr *= sc;
            mmax = nm;

            // ---- phase B: weighted aggregation, depth-2 pipelined y gathers ----
            int qa = __shfl_sync(0xffffffffu, pkl, 0);
            int qb = __shfl_sync(0xffffffffu, pkl, (cnt > 1) ? 1 : 0);
            float2 ya = *(const float2*)(d_Cbuf + (size_t)(qa & 8191) * 1280 + 1024 + (lane << 3));
            float2 yb = *(const float2*)(d_Cbuf + (size_t)(qb & 8191) * 1280 + 1024 + (lane << 3));
            for (int k = 0; k < cnt; k++) {
                int pk_c = qa; float2 y_c = ya;
                qa = qb; ya = yb;
                if (k + 2 < cnt) {
                    qb = __shfl_sync(0xffffffffu, pkl, k + 2);
                    yb = *(const float2*)(d_Cbuf + (size_t)(qb & 8191) * 1280 + 1024 + (lane << 3));
                }
                float wk = __shfl_sync(0xffffffffu, w, k);
                int x1s = (pk_c >> 13) & 3;
                float2 t2 = s_Ty2[x1s][lane];
                accl = fmaf(wk, y_c.x + t2.x, accl);
                accr = fmaf(wk, y_c.y + t2.y, accr);
            }
        }
        float inv = 1.f / lsum;
        float xlval = accl * inv + s_cl[lane];
        __nv_bfloat16 hb = __float2bfloat16(xlval);
        d_xl2h[v * 32 + lane] = hb;
        d_xr2f[v * 32 + lane] = accr * inv + s_cr[lane];
        float xd = warp_sum(a2v * __bfloat162float(hb));
        if (lane == 0) d_xldot[v] = xd;
    }
}

// ---------------- layer 2: transposed phase A (1 edge per lane) ----------------
__global__ void __launch_bounds__(256, 4) k_edge2(const float* __restrict__ att2,
                                                  const float* __restrict__ bias2, int n,
                                                  int nwarps) {
    __shared__ float s_we[4][32];
    __shared__ float s_a[32];
    __shared__ float s_a4[32];
    __shared__ float s_wedot[4];
    __shared__ float s_red[8][32];
    __shared__ __align__(16) uint4 s_stash[8][32][5];   // raw bf16 rows (64B) + 16B pad
    __shared__ float s_zb[8][4][32];                    // per-warp zbase
    int tid = threadIdx.x;
    if (tid < 128) ((float*)s_we)[tid] = ((const float*)d_we2)[tid];
    if (tid < 32) { float a = att2[tid]; s_a[tid] = a; s_a4[tid] = 0.4f * a; }
    __syncthreads();
    if (tid < 4) {
        float s = 0.f;
        for (int d = 0; d < 32; d++) s += s_a[d] * s_we[tid][d];
        s_wedot[tid] = s;
    }
    __syncthreads();
    int lane = tid & 31, wid = tid >> 5;
    int gwarp = blockIdx.x * 8 + wid;

    float a = s_a[lane];
    float a6 = 0.6f * a, a4l = 0.4f * a;
    float houtsum = 0.f;

    for (int v = gwarp; v < n; v += nwarps) {
        float xrv = d_xr2f[v * 32 + lane];
        float (*zb)[32] = s_zb[wid];
#pragma unroll
        for (int t = 0; t < 4; t++) zb[t][lane] = xrv + s_we[t][lane];
        __syncwarp();
        float xrdot = warp_sum(a * xrv);
        float xlv = __bfloat162float(d_xl2h[v * 32 + lane]);
        float z0 = xlv + zb[3][lane];
        float mmax = warp_sum(fmaf(a6, z0, a4l * fabsf(z0)));
        float lsum = 1.f, acc = xlv;
        int p0 = d_rowptr[v], p1 = d_rowptr[v + 1];
        for (int base = p0; base < p1; base += 32) {
            int idx = base + lane;
            bool valid = idx < p1;
            int pk = valid ? d_csr[idx].y : 0;
            int cnt = min(32, p1 - base);
            int s = pk & 0xFFFFF, t = pk >> 20;

            const uint4* xp = (const uint4*)&d_xl2h[s * 32];
            const float* zbp = zb[t];
            uint4* stp = s_stash[wid][lane];
            float ppa = 0.f;
#pragma unroll
            for (int q = 0; q < 4; q++) {
                uint4 w4 = xp[q];
                stp[q] = w4;
                const __nv_bfloat162* h = (const __nv_bfloat162*)&w4;
#pragma unroll
                for (int r = 0; r < 4; r++) {
                    float2 f = __bfloat1622float2(h[r]);
                    int d = q * 8 + r * 2;
                    float za = f.x + zbp[d];
                    float zc = f.y + zbp[d + 1];
                    ppa = fmaf(s_a4[d],     fabsf(za), ppa);
                    ppa = fmaf(s_a4[d + 1], fabsf(zc), ppa);
                }
            }
            float lin = 0.6f * (d_xldot[s] + xrdot + s_wedot[t]);
            float myscore = valid ? (ppa + lin) : -1e30f;

            float cmax = warp_max(myscore);
            float nm = fmaxf(mmax, cmax);
            float sc = __expf(mmax - nm);
            float w  = __expf(myscore - nm);
            float wsum = warp_sum(w);
            lsum = lsum * sc + wsum;
            acc *= sc;
            mmax = nm;
            __syncwarp();

            for (int k = 0; k < cnt; k++) {
                float wk = __shfl_sync(0xffffffffu, w, k);
                const __nv_bfloat16* row = (const __nv_bfloat16*)s_stash[wid][k];
                acc = fmaf(wk, __bfloat162float(row[lane]), acc);
            }
        }
        houtsum += acc / lsum + bias2[lane];
    }

    s_red[wid][lane] = houtsum;
    __syncthreads();
    if (wid == 0) {
        float s = 0.f;
#pragma unroll
        for (int w = 0; w < 8; w++) s += s_red[w][lane];
        atomicAdd(&d_gsum[lane], s);
    }
}

// ---------------- final: policy head + softmax ----------------
__global__ void k_final(const float* __restrict__ pW, const float* __restrict__ pb,
                        float* __restrict__ out, float invN) {
    __shared__ float g[32];
    __shared__ float red[64];
    int t = threadIdx.x;
    if (t < 32) g[t] = d_gsum[t] * invN;
    __syncthreads();
    float lg = pb[t];
    for (int j = 0; j < 32; j++) lg += g[j] * pW[j * 64 + t];
    red[t] = lg;
    __syncthreads();
    for (int o = 32; o > 0; o >>= 1) {
        if (t < o) red[t] = fmaxf(red[t], red[t + o]);
        __syncthreads();
    }
    float mx = red[0];
    __syncthreads();
    float ex = expf(lg - mx);
    red[t] = ex;
    __syncthreads();
    for (int o = 32; o > 0; o >>= 1) {
        if (t < o) red[t] += red[t + o];
        __syncthreads();
    }
    out[t] = ex / red[0];
}

// ---------------- launch (fork/join: k_tables overlaps scan/fill) ----------------
extern "C" void kernel_launch(void* const* d_in, const int* in_sizes, int n_in,
                              void* d_out, int out_size) {
    const int*   x         = (const int*)d_in[0];
    const int*   ei        = (const int*)d_in[1];
    const int*   eat       = (const int*)d_in[2];
    const float* text_emb  = (const float*)d_in[3];
    const float* type_emb  = (const float*)d_in[4];
    const float* flow_emb  = (const float*)d_in[5];
    const float* pos_table = (const float*)d_in[6];
    const float* pos_W     = (const float*)d_in[7];
    const float* pos_b     = (const float*)d_in[8];
    const float* c1_Wl  = (const float*)d_in[9];
    const float* c1_bl  = (const float*)d_in[10];
    const float* c1_Wr  = (const float*)d_in[11];
    const float* c1_br  = (const float*)d_in[12];
    const float* c1_We  = (const float*)d_in[13];
    const float* c1_att = (const float*)d_in[14];
    const float* c1_bias= (const float*)d_in[15];
    const float* c2_Wl  = (const float*)d_in[16];
    const float* c2_bl  = (const float*)d_in[17];
    const float* c2_Wr  = (const float*)d_in[18];
    const float* c2_br  = (const float*)d_in[19];
    const float* c2_We  = (const float*)d_in[20];
    const float* c2_att = (const float*)d_in[21];
    const float* c2_bias= (const float*)d_in[22];
    const float* pW     = (const float*)d_in[23];
    const float* pb     = (const float*)d_in[24];
    float* out = (float*)d_out;

    int N = in_sizes[0] / 2; if (N > NN) N = NN;
    int E = in_sizes[1] / 2; if (E > EE) E = EE;
    int Mt = in_sizes[3] / 64;

    int nb = (N + 255) / 256;
    int eb = (E + 255) / 256;
    int sb = (N + 1023) / 1024;

    int pblocks = 592;
    int nwarps = pblocks * 8;

    static cudaStream_t s2 = nullptr;
    static cudaEvent_t evFork = nullptr, evJoin = nullptr;
    if (s2 == nullptr) {
        cudaStreamCreateWithFlags(&s2, cudaStreamNonBlocking);
        cudaEventCreateWithFlags(&evFork, cudaEventDisableTiming);
        cudaEventCreateWithFlags(&evJoin, cudaEventDisableTiming);
    }

    k_init<<<nb, 256>>>(x, N);
    k_count<<<eb, 256>>>(ei, eat, E);
    k_pre<<<3, 256>>>(pos_table, pos_W, pos_b, flow_emb, type_emb,
                      c1_Wl, c1_bl, c1_Wr, c1_br, c1_We, c2_We,
                      c2_Wl, c2_Wr, c1_bias, c2_bl, c2_br, E);

    cudaEventRecord(evFork, 0);
    cudaStreamWaitEvent(s2, evFork, 0);
    dim3 g((Mt + 63) / 64, 9);
    k_tables<<<g, 256, 0, s2>>>(text_emb, Mt);
    cudaEventRecord(evJoin, s2);

    k_scan1<<<sb, 1024>>>(N);
    k_scan23<<<sb, 1024>>>(N);
    k_fill<<<eb, 256>>>(ei, eat, E);

    cudaStreamWaitEvent(0, evJoin, 0);

    k_edge1<<<pblocks, 256>>>(c1_att, c2_att, N, nwarps);
    k_edge2<<<pblocks, 256>>>(c2_att, c2_bias, N, nwarps);
    k_final<<<1, 64>>>(pW, pb, out, 1.0f / (float)N);
}